// round 2
// baseline (speedup 1.0000x reference)
#include <cuda_runtime.h>
#include <math.h>

// Problem dims
#define NB   4
#define NS   896
#define ND   1024
#define NH   16
#define NDH  64
#define NI   4096
#define NOUT 4096
#define NL   2
#define NM   128
#define NT   1024          // NM + NS
#define NBT  4096          // NB * NT

// ---------------- scratch (device globals; no allocation allowed) ----------------
__device__ float g_x[NBT * ND];                         // running activations [B,T,D]
__device__ float g_q[NBT * ND];                         // Q / generic temp
__device__ float g_k[NBT * ND];
__device__ float g_v[NBT * ND];
__device__ float g_t0[NBT * ND];                        // attention output
__device__ float g_inter[(size_t)NBT * NI];             // FFN intermediate
__device__ float g_scores[(size_t)NB * NH * NT * NT];   // attention scores

__device__ __forceinline__ float gelu_f(float x) {
    return 0.5f * x * (1.0f + erff(x * 0.7071067811865476f));
}

// ---------------- generic batched GEMM ----------------
// C[z] = act(alpha * A[z] @ B[z] + bias)
// A: [M,K] row-major (lda), B: [K,N] (ldb) or [N,K] if TRANSB, C: [M,N] (ldc)
// Per-batch offsets: off = (z/h)*outer + (z%h)*inner  for each operand.
// Grid covers M,N exactly (all dims divisible by tiles) -> no bounds checks.
template<int BM, int BN, int BK, int TM, int TN, bool TRANSB, int ACT>
__global__ void __launch_bounds__(256) gemm_kernel(
    const float* __restrict__ A, const float* __restrict__ Bm,
    const float* __restrict__ bias, float* __restrict__ C,
    int K, int lda, int ldb, int ldc,
    long long oA, long long iA, long long oB, long long iB,
    long long oC, long long iC, int h, float alpha)
{
    constexpr int THREADS = (BM / TM) * (BN / TN);
    __shared__ float As[BK][BM + 4];
    __shared__ float Bs[BK][BN + 4];

    const int z = blockIdx.z;
    A  += (long long)(z / h) * oA + (long long)(z % h) * iA;
    Bm += (long long)(z / h) * oB + (long long)(z % h) * iB;
    C  += (long long)(z / h) * oC + (long long)(z % h) * iC;

    const int bm = blockIdx.y * BM;
    const int bn = blockIdx.x * BN;
    const int tid = threadIdx.x;
    const int ty = tid / (BN / TN);
    const int tx = tid % (BN / TN);

    float acc[TM][TN];
#pragma unroll
    for (int i = 0; i < TM; i++)
#pragma unroll
        for (int j = 0; j < TN; j++) acc[i][j] = 0.0f;

    for (int k0 = 0; k0 < K; k0 += BK) {
#pragma unroll
        for (int idx = tid; idx < BM * BK; idx += THREADS) {
            int m = idx / BK, k = idx % BK;
            As[k][m] = A[(long long)(bm + m) * lda + (k0 + k)];
        }
        if (!TRANSB) {
#pragma unroll
            for (int idx = tid; idx < BK * BN; idx += THREADS) {
                int k = idx / BN, n = idx % BN;
                Bs[k][n] = Bm[(long long)(k0 + k) * ldb + (bn + n)];
            }
        } else {
#pragma unroll
            for (int idx = tid; idx < BK * BN; idx += THREADS) {
                int n = idx / BK, k = idx % BK;
                Bs[k][n] = Bm[(long long)(bn + n) * ldb + (k0 + k)];
            }
        }
        __syncthreads();

#pragma unroll
        for (int k = 0; k < BK; k++) {
            float a[TM], b[TN];
#pragma unroll
            for (int i = 0; i < TM; i += 4)
                *reinterpret_cast<float4*>(&a[i]) =
                    *reinterpret_cast<const float4*>(&As[k][ty * TM + i]);
#pragma unroll
            for (int j = 0; j < TN; j += 4)
                *reinterpret_cast<float4*>(&b[j]) =
                    *reinterpret_cast<const float4*>(&Bs[k][tx * TN + j]);
#pragma unroll
            for (int i = 0; i < TM; i++)
#pragma unroll
                for (int j = 0; j < TN; j++)
                    acc[i][j] = fmaf(a[i], b[j], acc[i][j]);
        }
        __syncthreads();
    }

#pragma unroll
    for (int i = 0; i < TM; i++) {
        const int m = bm + ty * TM + i;
#pragma unroll
        for (int j = 0; j < TN; j++) {
            const int n = bn + tx * TN + j;
            float v = acc[i][j] * alpha;
            if (bias) v += bias[n];
            if (ACT == 1) v = gelu_f(v);
            C[(long long)m * ldc + n] = v;
        }
    }
}

// ---------------- concat [mem_emb ; hidden_states] -> g_x ----------------
__global__ void concat_kernel(const float* __restrict__ hs, const float* __restrict__ mem) {
    int idx = blockIdx.x * blockDim.x + threadIdx.x;
    if (idx >= NBT * ND) return;
    int d = idx % ND;
    int t = (idx / ND) % NT;
    int b = idx / (ND * NT);
    g_x[idx] = (t < NM) ? mem[t * ND + d]
                        : hs[((size_t)(b * NS) + (t - NM)) * ND + d];
}

// ---------------- row softmax over g_scores (row length NT) ----------------
__global__ void __launch_bounds__(256) softmax_kernel() {
    float* row = g_scores + (size_t)blockIdx.x * NT;
    __shared__ float red[8];
    __shared__ float s_val;
    const int tid = threadIdx.x;
    float v[4];
#pragma unroll
    for (int i = 0; i < 4; i++) v[i] = row[tid + i * 256];
    float mx = fmaxf(fmaxf(v[0], v[1]), fmaxf(v[2], v[3]));
    for (int o = 16; o > 0; o >>= 1) mx = fmaxf(mx, __shfl_xor_sync(0xffffffffu, mx, o));
    if ((tid & 31) == 0) red[tid >> 5] = mx;
    __syncthreads();
    if (tid == 0) { float m = red[0]; for (int i = 1; i < 8; i++) m = fmaxf(m, red[i]); s_val = m; }
    __syncthreads();
    const float m = s_val;
    float s = 0.0f;
#pragma unroll
    for (int i = 0; i < 4; i++) { v[i] = expf(v[i] - m); s += v[i]; }
    for (int o = 16; o > 0; o >>= 1) s += __shfl_xor_sync(0xffffffffu, s, o);
    if ((tid & 31) == 0) red[tid >> 5] = s;
    __syncthreads();
    if (tid == 0) { float t = 0; for (int i = 0; i < 8; i++) t += red[i]; s_val = 1.0f / t; }
    __syncthreads();
    const float inv = s_val;
#pragma unroll
    for (int i = 0; i < 4; i++) row[tid + i * 256] = v[i] * inv;
}

// ---------------- x = LayerNorm(y + x) * g + b  (in place into g_x) ----------------
__global__ void __launch_bounds__(256) add_ln_kernel(
    const float* __restrict__ y, const float* __restrict__ g, const float* __restrict__ bt)
{
    __shared__ float red[8];
    __shared__ float s_mean, s_inv;
    const int tid = threadIdx.x;
    const size_t base = (size_t)blockIdx.x * ND;
    float v[4];
    float s = 0.0f;
#pragma unroll
    for (int i = 0; i < 4; i++) {
        int c = tid + i * 256;
        v[i] = y[base + c] + g_x[base + c];
        s += v[i];
    }
    for (int o = 16; o > 0; o >>= 1) s += __shfl_xor_sync(0xffffffffu, s, o);
    if ((tid & 31) == 0) red[tid >> 5] = s;
    __syncthreads();
    if (tid == 0) { float t = 0; for (int i = 0; i < 8; i++) t += red[i]; s_mean = t * (1.0f / ND); }
    __syncthreads();
    const float mean = s_mean;
    float vs = 0.0f;
#pragma unroll
    for (int i = 0; i < 4; i++) { float d = v[i] - mean; vs += d * d; }
    for (int o = 16; o > 0; o >>= 1) vs += __shfl_xor_sync(0xffffffffu, vs, o);
    if ((tid & 31) == 0) red[tid >> 5] = vs;
    __syncthreads();
    if (tid == 0) { float t = 0; for (int i = 0; i < 8; i++) t += red[i]; s_inv = rsqrtf(t * (1.0f / ND) + 1e-12f); }
    __syncthreads();
    const float inv = s_inv;
#pragma unroll
    for (int i = 0; i < 4; i++) {
        int c = tid + i * 256;
        g_x[base + c] = (v[i] - mean) * inv * g[c] + bt[c];
    }
}

// ---------------- read_out = x[:, :NM] ----------------
__global__ void readout_kernel(float* __restrict__ out) {
    int idx = blockIdx.x * blockDim.x + threadIdx.x;
    if (idx >= NB * NM * ND) return;
    int d = idx % ND;
    int t = (idx / ND) % NM;
    int b = idx / (ND * NM);
    out[(size_t)NB * NS * NOUT + idx] = g_x[((size_t)b * NT + t) * ND + d];
}

extern "C" void kernel_launch(void* const* d_in, const int* in_sizes, int n_in,
                              void* d_out, int out_size) {
    const float* hs   = (const float*)d_in[0];
    const float* mem  = (const float*)d_in[1];
    const float* Wq   = (const float*)d_in[2];
    const float* bq   = (const float*)d_in[3];
    const float* Wk   = (const float*)d_in[4];
    const float* bk   = (const float*)d_in[5];
    const float* Wv   = (const float*)d_in[6];
    const float* bv   = (const float*)d_in[7];
    const float* Wo   = (const float*)d_in[8];
    const float* bo   = (const float*)d_in[9];
    const float* ln1g = (const float*)d_in[10];
    const float* ln1b = (const float*)d_in[11];
    const float* Wm   = (const float*)d_in[12];
    const float* bm   = (const float*)d_in[13];
    const float* Wr   = (const float*)d_in[14];
    const float* br   = (const float*)d_in[15];
    const float* ln2g = (const float*)d_in[16];
    const float* ln2b = (const float*)d_in[17];
    const float* Wp   = (const float*)d_in[18];
    const float* bp   = (const float*)d_in[19];
    float* out = (float*)d_out;

    static float *p_x = nullptr, *p_q, *p_k, *p_v, *p_t0, *p_inter, *p_scores;
    if (!p_x) {
        cudaGetSymbolAddress((void**)&p_x,      g_x);
        cudaGetSymbolAddress((void**)&p_q,      g_q);
        cudaGetSymbolAddress((void**)&p_k,      g_k);
        cudaGetSymbolAddress((void**)&p_v,      g_v);
        cudaGetSymbolAddress((void**)&p_t0,     g_t0);
        cudaGetSymbolAddress((void**)&p_inter,  g_inter);
        cudaGetSymbolAddress((void**)&p_scores, g_scores);
    }

    const long long Z = 0;
    {
        int n = NBT * ND;
        concat_kernel<<<(n + 255) / 256, 256>>>(hs, mem);
    }

    for (int l = 0; l < NL; l++) {
        const float* wq = Wq + (size_t)l * ND * ND;
        const float* wk = Wk + (size_t)l * ND * ND;
        const float* wv = Wv + (size_t)l * ND * ND;
        const float* wo = Wo + (size_t)l * ND * ND;
        const float* wm = Wm + (size_t)l * ND * NI;
        const float* wr = Wr + (size_t)l * NI * ND;

        // Q, K, V projections: [4096,1024] = x @ W + b
        gemm_kernel<128,128,8,8,8,false,0><<<dim3(ND/128, NBT/128, 1), 256>>>(
            p_x, wq, bq + l*ND, p_q, ND, ND, ND, ND, Z,Z,Z,Z,Z,Z, 1, 1.0f);
        gemm_kernel<128,128,8,8,8,false,0><<<dim3(ND/128, NBT/128, 1), 256>>>(
            p_x, wk, bk + l*ND, p_k, ND, ND, ND, ND, Z,Z,Z,Z,Z,Z, 1, 1.0f);
        gemm_kernel<128,128,8,8,8,false,0><<<dim3(ND/128, NBT/128, 1), 256>>>(
            p_x, wv, bv + l*ND, p_v, ND, ND, ND, ND, Z,Z,Z,Z,Z,Z, 1, 1.0f);

        // scores[b,h] = Q[b,h] @ K[b,h]^T / 8   (batched, TRANSB)
        gemm_kernel<128,128,8,8,8,true,0><<<dim3(NT/128, NT/128, NB*NH), 256>>>(
            p_q, p_k, nullptr, p_scores, NDH, ND, ND, NT,
            (long long)NT*ND, (long long)NDH,
            (long long)NT*ND, (long long)NDH,
            (long long)NH*NT*NT, (long long)NT*NT, NH, 0.125f);

        softmax_kernel<<<NB*NH*NT, 256>>>();

        // attn_out[b,h] = P[b,h] @ V[b,h]   (batched, N=64)
        gemm_kernel<64,64,8,4,4,false,0><<<dim3(1, NT/64, NB*NH), 256>>>(
            p_scores, p_v, nullptr, p_t0, NT, NT, ND, ND,
            (long long)NH*NT*NT, (long long)NT*NT,
            (long long)NT*ND, (long long)NDH,
            (long long)NT*ND, (long long)NDH, NH, 1.0f);

        // O projection
        gemm_kernel<128,128,8,8,8,false,0><<<dim3(ND/128, NBT/128, 1), 256>>>(
            p_t0, wo, bo + l*ND, p_q, ND, ND, ND, ND, Z,Z,Z,Z,Z,Z, 1, 1.0f);
        add_ln_kernel<<<NBT, 256>>>(p_q, ln1g + l*ND, ln1b + l*ND);

        // FFN up + GELU
        gemm_kernel<128,128,8,8,8,false,1><<<dim3(NI/128, NBT/128, 1), 256>>>(
            p_x, wm, bm + l*NI, p_inter, ND, ND, NI, NI, Z,Z,Z,Z,Z,Z, 1, 1.0f);
        // FFN down
        gemm_kernel<128,128,8,8,8,false,0><<<dim3(ND/128, NBT/128, 1), 256>>>(
            p_inter, wr, br + l*ND, p_q, NI, NI, ND, ND, Z,Z,Z,Z,Z,Z, 1, 1.0f);
        add_ln_kernel<<<NBT, 256>>>(p_q, ln2g + l*ND, ln2b + l*ND);
    }

    // out = gelu(x[:, NM:] @ Wp + bp)  (batched over B, rows offset by NM)
    gemm_kernel<128,128,8,8,8,false,1><<<dim3(NOUT/128, NS/128, NB), 256>>>(
        p_x + (size_t)NM*ND, Wp, bp, out, ND, ND, NOUT, NOUT,
        (long long)NT*ND, Z, Z, Z, (long long)NS*NOUT, Z, 1, 1.0f);

    {
        int n = NB * NM * ND;
        readout_kernel<<<(n + 255) / 256, 256>>>(out);
    }
}

// round 4
// speedup vs baseline: 2.2786x; 2.2786x over previous
#include <cuda_runtime.h>
#include <cuda_bf16.h>
#include <math.h>
#include <stdint.h>

#define NB   4
#define NS   896
#define ND   1024
#define NH   16
#define NDH  64
#define NI   4096
#define NOUT 4096
#define NL   2
#define NM   128
#define NT   1024
#define NBT  4096

typedef __nv_bfloat16 bf16;
typedef long long ll;

__device__ float g_x[NBT * ND];
__device__ float g_y[NBT * ND];
__device__ float g_scores[(size_t)NB * NH * NT * NT];
__device__ bf16  g_xh[NBT * ND],  g_xl[NBT * ND];
__device__ bf16  g_qh[NBT * ND],  g_ql[NBT * ND];
__device__ bf16  g_kh[NBT * ND],  g_kl[NBT * ND];
__device__ bf16  g_vth[NBT * ND], g_vtl[NBT * ND];
__device__ bf16  g_t0h[NBT * ND], g_t0l[NBT * ND];
__device__ bf16  g_ph[(size_t)NB * NH * NT * NT], g_pl[(size_t)NB * NH * NT * NT];
__device__ bf16  g_ih[(size_t)NBT * NI], g_il[(size_t)NBT * NI];
#define WPL (4 * ND * ND + ND * NI + NI * ND)
#define WELEMS (NL * WPL + ND * NOUT)
__device__ bf16  g_wh[WELEMS], g_wl[WELEMS];

__device__ __forceinline__ uint32_t smem_u32(const void* p) {
    uint32_t a;
    asm("{ .reg .u64 t; cvta.to.shared.u64 t, %1; cvt.u32.u64 %0, t; }" : "=r"(a) : "l"(p));
    return a;
}
__device__ __forceinline__ float gelu_f(float x) {
    return 0.5f * x * (1.0f + erff(x * 0.7071067811865476f));
}
__device__ __forceinline__ void split2(float v, bf16& h, bf16& l) {
    h = __float2bfloat16(v);
    l = __float2bfloat16(v - __bfloat162float(h));
}
__device__ __forceinline__ void ldsm4(uint32_t& r0, uint32_t& r1, uint32_t& r2, uint32_t& r3, uint32_t a) {
    asm volatile("ldmatrix.sync.aligned.m8n8.x4.shared.b16 {%0,%1,%2,%3}, [%4];"
                 : "=r"(r0), "=r"(r1), "=r"(r2), "=r"(r3) : "r"(a));
}
__device__ __forceinline__ void mma16816(float* c, const uint32_t* a, const uint32_t* b) {
    asm volatile("mma.sync.aligned.m16n8k16.row.col.f32.bf16.bf16.f32 "
                 "{%0,%1,%2,%3},{%4,%5,%6,%7},{%8,%9},{%0,%1,%2,%3};"
                 : "+f"(c[0]), "+f"(c[1]), "+f"(c[2]), "+f"(c[3])
                 : "r"(a[0]), "r"(a[1]), "r"(a[2]), "r"(a[3]), "r"(b[0]), "r"(b[1]));
}
__device__ __forceinline__ void cpasync16(uint32_t dst, const void* src) {
    asm volatile("cp.async.cg.shared.global [%0], [%1], 16;" :: "r"(dst), "l"(src));
}
__device__ __forceinline__ void cpcommit() { asm volatile("cp.async.commit_group;" ::: "memory"); }
template<int N> __device__ __forceinline__ void cpwait() {
    asm volatile("cp.async.wait_group %0;" :: "n"(N) : "memory");
}
// swizzled offset inside a [rows][64 bf16] tile (128B rows, SW128)
__device__ __forceinline__ uint32_t swoff(int r, int c16) {
    return (uint32_t)(r * 128 + ((c16 ^ (r & 7)) * 16));
}

// ---------------- split-bf16 warp-MMA GEMM ----------------
// D[128,BN] = act(alpha*((Ah+Al)[128,K] @ ((Bh+Bl)[BN,K])^T) + bias)
// OUTM: 0=fp32 C, 1=bf16 hi/lo C, 2=bf16 hi/lo transposed C (Ct[n*ldc+m])
template<int BN, int ACT, int OUTM>
__global__ void __launch_bounds__(256) tgemm(
    const bf16* __restrict__ Ah, const bf16* __restrict__ Al,
    const bf16* __restrict__ Bh, const bf16* __restrict__ Bl,
    const float* __restrict__ bias, float alpha,
    float* __restrict__ Cf, bf16* __restrict__ Ch, bf16* __restrict__ Cl,
    int K, int lda, int ldb, int ldc,
    ll oA, ll iA, ll oB, ll iB, ll oC, ll iC, int h)
{
    constexpr int ABYTES = 128 * 128;
    constexpr int BBYTES = BN * 128;
    constexpr int STAGE  = 2 * ABYTES + 2 * BBYTES;
    constexpr int WN     = BN / 2;      // warp n extent
    constexpr int NT8    = WN / 8;      // 8x8-n tiles per warp

    extern __shared__ __align__(128) char smem[];
    const uint32_t sb = smem_u32(smem);
    const int tid = threadIdx.x, lane = tid & 31, wid = tid >> 5;
    const int wm = wid >> 1, wn = wid & 1;

    const int z = blockIdx.z;
    const ll aoff = (ll)(z / h) * oA + (ll)(z % h) * iA;
    const ll boff = (ll)(z / h) * oB + (ll)(z % h) * iB;
    const ll coff = (ll)(z / h) * oC + (ll)(z % h) * iC;
    const int bm = blockIdx.y * 128;
    const int bn = blockIdx.x * BN;
    const bf16* a0h = Ah + aoff + (ll)bm * lda;
    const bf16* a0l = Al + aoff + (ll)bm * lda;
    const bf16* b0h = Bh + boff + (ll)bn * ldb;
    const bf16* b0l = Bl + boff + (ll)bn * ldb;

    float acc[2][NT8][4];
#pragma unroll
    for (int i = 0; i < 2; i++)
#pragma unroll
        for (int j = 0; j < NT8; j++)
#pragma unroll
            for (int t = 0; t < 4; t++) acc[i][j][t] = 0.0f;

    const int nch = K >> 6;

    // ldmatrix per-lane address components
    const int aRow = (lane & 7) | (((lane >> 3) & 1) << 3);
    const int aC   = lane >> 4;
    const int bRow = (lane & 7) | (((lane >> 4) & 1) << 3);
    const int bC   = (lane >> 3) & 1;

    auto issue = [&](int c, int s) {
        const int k0 = c * 64;
        const uint32_t base = sb + s * STAGE;
        constexpr int TOT = (2 * 128 + 2 * BN) * 8;
#pragma unroll 4
        for (int u = tid; u < TOT; u += 256) {
            const int chunk = u & 7, row = u >> 3;
            const bf16* src; uint32_t dbase; int r, ld;
            if (row < 128)            { src = a0h; r = row;            dbase = base;                       ld = lda; }
            else if (row < 256)       { src = a0l; r = row - 128;      dbase = base + ABYTES;              ld = lda; }
            else if (row < 256 + BN)  { src = b0h; r = row - 256;      dbase = base + 2 * ABYTES;          ld = ldb; }
            else                      { src = b0l; r = row - 256 - BN; dbase = base + 2 * ABYTES + BBYTES; ld = ldb; }
            cpasync16(dbase + swoff(r, chunk), src + (ll)r * ld + k0 + chunk * 8);
        }
    };

    issue(0, 0);
    cpcommit();

    for (int c = 0; c < nch; c++) {
        if (c + 1 < nch) { issue(c + 1, (c + 1) & 1); cpcommit(); cpwait<1>(); }
        else             { cpwait<0>(); }
        __syncthreads();

        const uint32_t tAh = sb + (c & 1) * STAGE;
        const uint32_t tAl = tAh + ABYTES;
        const uint32_t tBh = tAh + 2 * ABYTES;
        const uint32_t tBl = tBh + BBYTES;

#pragma unroll
        for (int ks = 0; ks < 4; ks++) {
            uint32_t ah[2][4], al[2][4], bh[NT8][2], blr[NT8][2];
#pragma unroll
            for (int mt = 0; mt < 2; mt++) {
                const int r = wm * 32 + mt * 16 + aRow;
                const int c16 = ks * 2 + aC;
                ldsm4(ah[mt][0], ah[mt][1], ah[mt][2], ah[mt][3], tAh + swoff(r, c16));
                ldsm4(al[mt][0], al[mt][1], al[mt][2], al[mt][3], tAl + swoff(r, c16));
            }
#pragma unroll
            for (int nt2 = 0; nt2 < NT8 / 2; nt2++) {
                const int r = wn * WN + nt2 * 16 + bRow;
                const int c16 = ks * 2 + bC;
                ldsm4(bh[2*nt2][0], bh[2*nt2][1], bh[2*nt2+1][0], bh[2*nt2+1][1], tBh + swoff(r, c16));
                ldsm4(blr[2*nt2][0], blr[2*nt2][1], blr[2*nt2+1][0], blr[2*nt2+1][1], tBl + swoff(r, c16));
            }
#pragma unroll
            for (int mt = 0; mt < 2; mt++)
#pragma unroll
                for (int nt = 0; nt < NT8; nt++) {
                    mma16816(acc[mt][nt], ah[mt], bh[nt]);
                    mma16816(acc[mt][nt], ah[mt], blr[nt]);
                    mma16816(acc[mt][nt], al[mt], bh[nt]);
                }
        }
        __syncthreads();
    }

    // ---------------- epilogue ----------------
    const int gid = lane >> 2, tig2 = (lane & 3) * 2;
#pragma unroll
    for (int mt = 0; mt < 2; mt++) {
#pragma unroll
        for (int nt = 0; nt < NT8; nt++) {
            const int n = bn + wn * WN + nt * 8 + tig2;
            float bv0 = 0.f, bv1 = 0.f;
            if (bias) { bv0 = bias[n]; bv1 = bias[n + 1]; }
#pragma unroll
            for (int hf = 0; hf < 2; hf++) {
                const int m = bm + wm * 32 + mt * 16 + gid + hf * 8;
                float v0 = acc[mt][nt][hf * 2]     * alpha + bv0;
                float v1 = acc[mt][nt][hf * 2 + 1] * alpha + bv1;
                if (ACT) { v0 = gelu_f(v0); v1 = gelu_f(v1); }
                if (OUTM == 0) {
                    *reinterpret_cast<float2*>(Cf + coff + (ll)m * ldc + n) = make_float2(v0, v1);
                } else if (OUTM == 1) {
                    union { uint32_t u; bf16 b[2]; } H, L;
                    split2(v0, H.b[0], L.b[0]); split2(v1, H.b[1], L.b[1]);
                    *reinterpret_cast<uint32_t*>(Ch + coff + (ll)m * ldc + n) = H.u;
                    *reinterpret_cast<uint32_t*>(Cl + coff + (ll)m * ldc + n) = L.u;
                } else {
                    bf16 h0, l0, h1, l1;
                    split2(v0, h0, l0); split2(v1, h1, l1);
                    Ch[coff + (ll)n * ldc + m] = h0;       Cl[coff + (ll)n * ldc + m] = l0;
                    Ch[coff + (ll)(n + 1) * ldc + m] = h1; Cl[coff + (ll)(n + 1) * ldc + m] = l1;
                }
            }
        }
    }
}

// W[K,N] -> Th/Tl[N,K]
__global__ void __launch_bounds__(256) wsplit_kernel(const float* __restrict__ W,
                                                     bf16* __restrict__ Th, bf16* __restrict__ Tl,
                                                     int K, int N) {
    __shared__ float t[32][33];
    const int n0 = blockIdx.x * 32, k0 = blockIdx.y * 32;
    const int tx = threadIdx.x, ty = threadIdx.y;
#pragma unroll
    for (int i = 0; i < 4; i++)
        t[ty + i * 8][tx] = W[(ll)(k0 + ty + i * 8) * N + n0 + tx];
    __syncthreads();
#pragma unroll
    for (int i = 0; i < 4; i++) {
        int n = ty + i * 8;
        bf16 h, l; split2(t[tx][n], h, l);
        Th[(ll)(n0 + n) * K + k0 + tx] = h;
        Tl[(ll)(n0 + n) * K + k0 + tx] = l;
    }
}

__global__ void concat_kernel(const float* __restrict__ hs, const float* __restrict__ mem) {
    int i4 = blockIdx.x * blockDim.x + threadIdx.x;
    if (i4 >= NBT * ND / 4) return;
    int idx = i4 * 4;
    int d = idx % ND;
    int t = (idx / ND) % NT;
    int b = idx / (ND * NT);
    float4 v = (t < NM) ? *reinterpret_cast<const float4*>(mem + t * ND + d)
                        : *reinterpret_cast<const float4*>(hs + ((size_t)(b * NS + t - NM)) * ND + d);
    *reinterpret_cast<float4*>(g_x + idx) = v;
    union { uint2 u; bf16 b[4]; } H, L;
    split2(v.x, H.b[0], L.b[0]); split2(v.y, H.b[1], L.b[1]);
    split2(v.z, H.b[2], L.b[2]); split2(v.w, H.b[3], L.b[3]);
    *reinterpret_cast<uint2*>(g_xh + idx) = H.u;
    *reinterpret_cast<uint2*>(g_xl + idx) = L.u;
}

__global__ void __launch_bounds__(256) softmax_kernel() {
    const size_t ro = (size_t)blockIdx.x * NT;
    __shared__ float red[8];
    __shared__ float sv;
    const int tid = threadIdx.x;
    float4 v = *reinterpret_cast<const float4*>(g_scores + ro + tid * 4);
    float mx = fmaxf(fmaxf(v.x, v.y), fmaxf(v.z, v.w));
    for (int o = 16; o > 0; o >>= 1) mx = fmaxf(mx, __shfl_xor_sync(0xffffffffu, mx, o));
    if ((tid & 31) == 0) red[tid >> 5] = mx;
    __syncthreads();
    if (tid == 0) { float m = red[0]; for (int i = 1; i < 8; i++) m = fmaxf(m, red[i]); sv = m; }
    __syncthreads();
    const float m = sv;
    v.x = expf(v.x - m); v.y = expf(v.y - m); v.z = expf(v.z - m); v.w = expf(v.w - m);
    float s = v.x + v.y + v.z + v.w;
    for (int o = 16; o > 0; o >>= 1) s += __shfl_xor_sync(0xffffffffu, s, o);
    if ((tid & 31) == 0) red[tid >> 5] = s;
    __syncthreads();
    if (tid == 0) { float t = 0; for (int i = 0; i < 8; i++) t += red[i]; sv = 1.0f / t; }
    __syncthreads();
    const float inv = sv;
    union { uint2 u; bf16 b[4]; } H, L;
    split2(v.x * inv, H.b[0], L.b[0]); split2(v.y * inv, H.b[1], L.b[1]);
    split2(v.z * inv, H.b[2], L.b[2]); split2(v.w * inv, H.b[3], L.b[3]);
    *reinterpret_cast<uint2*>(g_ph + ro + tid * 4) = H.u;
    *reinterpret_cast<uint2*>(g_pl + ro + tid * 4) = L.u;
}

__global__ void __launch_bounds__(256) add_ln_kernel(const float* __restrict__ y,
                                                     const float* __restrict__ gam,
                                                     const float* __restrict__ bet) {
    __shared__ float red[8];
    __shared__ float s0, s1;
    const int tid = threadIdx.x;
    const size_t base = (size_t)blockIdx.x * ND;
    const int c = tid * 4;
    float4 a = *reinterpret_cast<const float4*>(y + base + c);
    float4 xo = *reinterpret_cast<const float4*>(g_x + base + c);
    float v0 = a.x + xo.x, v1 = a.y + xo.y, v2 = a.z + xo.z, v3 = a.w + xo.w;
    float s = v0 + v1 + v2 + v3;
    for (int o = 16; o > 0; o >>= 1) s += __shfl_xor_sync(0xffffffffu, s, o);
    if ((tid & 31) == 0) red[tid >> 5] = s;
    __syncthreads();
    if (tid == 0) { float t = 0; for (int i = 0; i < 8; i++) t += red[i]; s0 = t * (1.0f / ND); }
    __syncthreads();
    const float mean = s0;
    float d0 = v0 - mean, d1 = v1 - mean, d2 = v2 - mean, d3 = v3 - mean;
    float vs = d0*d0 + d1*d1 + d2*d2 + d3*d3;
    for (int o = 16; o > 0; o >>= 1) vs += __shfl_xor_sync(0xffffffffu, vs, o);
    if ((tid & 31) == 0) red[tid >> 5] = vs;
    __syncthreads();
    if (tid == 0) { float t = 0; for (int i = 0; i < 8; i++) t += red[i]; s1 = rsqrtf(t * (1.0f / ND) + 1e-12f); }
    __syncthreads();
    const float inv = s1;
    float4 gv = *reinterpret_cast<const float4*>(gam + c);
    float4 bv = *reinterpret_cast<const float4*>(bet + c);
    float r0 = d0*inv*gv.x + bv.x, r1 = d1*inv*gv.y + bv.y;
    float r2 = d2*inv*gv.z + bv.z, r3 = d3*inv*gv.w + bv.w;
    *reinterpret_cast<float4*>(g_x + base + c) = make_float4(r0, r1, r2, r3);
    union { uint2 u; bf16 b[4]; } H, L;
    split2(r0, H.b[0], L.b[0]); split2(r1, H.b[1], L.b[1]);
    split2(r2, H.b[2], L.b[2]); split2(r3, H.b[3], L.b[3]);
    *reinterpret_cast<uint2*>(g_xh + base + c) = H.u;
    *reinterpret_cast<uint2*>(g_xl + base + c) = L.u;
}

__global__ void readout_kernel(float* __restrict__ out) {
    int idx = blockIdx.x * blockDim.x + threadIdx.x;
    if (idx >= NB * NM * ND) return;
    int d = idx % ND;
    int t = (idx / ND) % NM;
    int b = idx / (ND * NM);
    out[(size_t)NB * NS * NOUT + idx] = g_x[((size_t)b * NT + t) * ND + d];
}

#define S128 (2 * (2 * 128 * 128 + 2 * 128 * 128))   // 131072
#define S64  (2 * (2 * 128 * 128 + 2 * 64 * 128))    // 98304

extern "C" void kernel_launch(void* const* d_in, const int* in_sizes, int n_in,
                              void* d_out, int out_size) {
    const float* hs   = (const float*)d_in[0];
    const float* mem  = (const float*)d_in[1];
    const float* Wq   = (const float*)d_in[2];
    const float* bq   = (const float*)d_in[3];
    const float* Wk   = (const float*)d_in[4];
    const float* bk   = (const float*)d_in[5];
    const float* Wv   = (const float*)d_in[6];
    const float* bv   = (const float*)d_in[7];
    const float* Wo   = (const float*)d_in[8];
    const float* bo   = (const float*)d_in[9];
    const float* ln1g = (const float*)d_in[10];
    const float* ln1b = (const float*)d_in[11];
    const float* Wm   = (const float*)d_in[12];
    const float* bmv  = (const float*)d_in[13];
    const float* Wr   = (const float*)d_in[14];
    const float* br   = (const float*)d_in[15];
    const float* ln2g = (const float*)d_in[16];
    const float* ln2b = (const float*)d_in[17];
    const float* Wp   = (const float*)d_in[18];
    const float* bp   = (const float*)d_in[19];
    float* out = (float*)d_out;

    static bf16 *wh = nullptr, *wl, *xh, *xl, *qh, *ql, *kh, *kl;
    static bf16 *vth, *vtl, *t0h, *t0l, *ph, *pl, *ih, *il;
    static float *px, *py, *psc;
    if (!wh) {
        cudaGetSymbolAddress((void**)&wh, g_wh);   cudaGetSymbolAddress((void**)&wl, g_wl);
        cudaGetSymbolAddress((void**)&xh, g_xh);   cudaGetSymbolAddress((void**)&xl, g_xl);
        cudaGetSymbolAddress((void**)&qh, g_qh);   cudaGetSymbolAddress((void**)&ql, g_ql);
        cudaGetSymbolAddress((void**)&kh, g_kh);   cudaGetSymbolAddress((void**)&kl, g_kl);
        cudaGetSymbolAddress((void**)&vth, g_vth); cudaGetSymbolAddress((void**)&vtl, g_vtl);
        cudaGetSymbolAddress((void**)&t0h, g_t0h); cudaGetSymbolAddress((void**)&t0l, g_t0l);
        cudaGetSymbolAddress((void**)&ph, g_ph);   cudaGetSymbolAddress((void**)&pl, g_pl);
        cudaGetSymbolAddress((void**)&ih, g_ih);   cudaGetSymbolAddress((void**)&il, g_il);
        cudaGetSymbolAddress((void**)&px, g_x);    cudaGetSymbolAddress((void**)&py, g_y);
        cudaGetSymbolAddress((void**)&psc, g_scores);
        cudaFuncSetAttribute((const void*)tgemm<128,0,0>, cudaFuncAttributeMaxDynamicSharedMemorySize, S128);
        cudaFuncSetAttribute((const void*)tgemm<128,0,1>, cudaFuncAttributeMaxDynamicSharedMemorySize, S128);
        cudaFuncSetAttribute((const void*)tgemm<128,0,2>, cudaFuncAttributeMaxDynamicSharedMemorySize, S128);
        cudaFuncSetAttribute((const void*)tgemm<64,0,1>,  cudaFuncAttributeMaxDynamicSharedMemorySize, S64);
        cudaFuncSetAttribute((const void*)tgemm<128,1,1>, cudaFuncAttributeMaxDynamicSharedMemorySize, S128);
        cudaFuncSetAttribute((const void*)tgemm<128,1,0>, cudaFuncAttributeMaxDynamicSharedMemorySize, S128);
    }

    const ll Z = 0;
    const ll DD = (ll)ND * ND;
    dim3 t32(32, 8);

    for (int l = 0; l < NL; l++) {
        ll o = (ll)l * WPL;
        wsplit_kernel<<<dim3(ND/32, ND/32), t32>>>(Wq + l*DD, wh + o,        wl + o,        ND, ND);
        wsplit_kernel<<<dim3(ND/32, ND/32), t32>>>(Wk + l*DD, wh + o + DD,   wl + o + DD,   ND, ND);
        wsplit_kernel<<<dim3(ND/32, ND/32), t32>>>(Wv + l*DD, wh + o + 2*DD, wl + o + 2*DD, ND, ND);
        wsplit_kernel<<<dim3(ND/32, ND/32), t32>>>(Wo + l*DD, wh + o + 3*DD, wl + o + 3*DD, ND, ND);
        wsplit_kernel<<<dim3(NI/32, ND/32), t32>>>(Wm + (ll)l*ND*NI, wh + o + 4*DD, wl + o + 4*DD, ND, NI);
        wsplit_kernel<<<dim3(ND/32, NI/32), t32>>>(Wr + (ll)l*NI*ND, wh + o + 4*DD + (ll)ND*NI,
                                                   wl + o + 4*DD + (ll)ND*NI, NI, ND);
    }
    wsplit_kernel<<<dim3(NOUT/32, ND/32), t32>>>(Wp, wh + (ll)NL*WPL, wl + (ll)NL*WPL, ND, NOUT);

    concat_kernel<<<(NBT * ND / 4 + 255) / 256, 256>>>(hs, mem);

    for (int l = 0; l < NL; l++) {
        ll o = (ll)l * WPL;
        const bf16 *wqh = wh + o,        *wql = wl + o;
        const bf16 *wkh = wh + o + DD,   *wkl = wl + o + DD;
        const bf16 *wvh = wh + o + 2*DD, *wvl = wl + o + 2*DD;
        const bf16 *woh = wh + o + 3*DD, *wol = wl + o + 3*DD;
        const bf16 *wmh = wh + o + 4*DD, *wml = wl + o + 4*DD;
        const bf16 *wrh = wh + o + 4*DD + (ll)ND*NI, *wrl = wl + o + 4*DD + (ll)ND*NI;

        tgemm<128,0,1><<<dim3(8, 32, 1), 256, S128>>>(xh, xl, wqh, wql, bq + l*ND, 1.f,
            nullptr, qh, ql, ND, ND, ND, ND, Z,Z,Z,Z,Z,Z, 1);
        tgemm<128,0,1><<<dim3(8, 32, 1), 256, S128>>>(xh, xl, wkh, wkl, bk + l*ND, 1.f,
            nullptr, kh, kl, ND, ND, ND, ND, Z,Z,Z,Z,Z,Z, 1);
        tgemm<128,0,2><<<dim3(8, 32, 1), 256, S128>>>(xh, xl, wvh, wvl, bv + l*ND, 1.f,
            nullptr, vth, vtl, ND, ND, ND, NBT, Z,Z,Z,Z,Z,Z, 1);

        tgemm<128,0,0><<<dim3(8, 8, NB*NH), 256, S128>>>(qh, ql, kh, kl, nullptr, 0.125f,
            psc, nullptr, nullptr, NDH, ND, ND, NT,
            (ll)NT*ND, (ll)NDH, (ll)NT*ND, (ll)NDH, (ll)NH*NT*NT, (ll)NT*NT, NH);

        softmax_kernel<<<NB*NH*NT, 256>>>();

        tgemm<64,0,1><<<dim3(1, 8, NB*NH), 256, S64>>>(ph, pl, vth, vtl, nullptr, 1.f,
            nullptr, t0h, t0l, NT, NT, NBT, ND,
            (ll)NH*NT*NT, (ll)NT*NT, (ll)NT, (ll)NDH*NBT, (ll)NT*ND, (ll)NDH, NH);

        tgemm<128,0,0><<<dim3(8, 32, 1), 256, S128>>>(t0h, t0l, woh, wol, bo + l*ND, 1.f,
            py, nullptr, nullptr, ND, ND, ND, ND, Z,Z,Z,Z,Z,Z, 1);
        add_ln_kernel<<<NBT, 256>>>(py, ln1g + l*ND, ln1b + l*ND);

        tgemm<128,1,1><<<dim3(32, 32, 1), 256, S128>>>(xh, xl, wmh, wml, bmv + l*NI, 1.f,
            nullptr, ih, il, ND, ND, ND, NI, Z,Z,Z,Z,Z,Z, 1);
        tgemm<128,0,0><<<dim3(8, 32, 1), 256, S128>>>(ih, il, wrh, wrl, br + l*ND, 1.f,
            py, nullptr, nullptr, NI, NI, NI, ND, Z,Z,Z,Z,Z,Z, 1);
        add_ln_kernel<<<NBT, 256>>>(py, ln2g + l*ND, ln2b + l*ND);
    }

    tgemm<128,1,0><<<dim3(32, 7, NB), 256, S128>>>(xh + NM*ND, xl + NM*ND,
        wh + (ll)NL*WPL, wl + (ll)NL*WPL, bp, 1.f,
        out, nullptr, nullptr, ND, ND, ND, NOUT,
        (ll)NT*ND, Z, Z, Z, (ll)NS*NOUT, Z, 1);

    readout_kernel<<<(NB * NM * ND + 255) / 256, 256>>>(out);
}

// round 5
// speedup vs baseline: 3.4381x; 1.5088x over previous
#include <cuda_runtime.h>
#include <cuda_fp16.h>
#include <math.h>
#include <stdint.h>

#define NB   4
#define NS   896
#define ND   1024
#define NH   16
#define NDH  64
#define NI   4096
#define NOUT 4096
#define NL   2
#define NM   128
#define NT   1024
#define NBT  4096

typedef __half h16;
typedef long long ll;

__device__ float g_x[NBT * ND];
__device__ float g_y[NBT * ND];
__device__ float g_scores[(size_t)NB * NH * NT * NT];
__device__ h16  g_xh[NBT * ND],  g_xl[NBT * ND];
__device__ h16  g_qh[NBT * ND],  g_ql[NBT * ND];
__device__ h16  g_kh[NBT * ND];
__device__ h16  g_vth[NBT * ND];
__device__ h16  g_t0h[NBT * ND], g_t0l[NBT * ND];
__device__ h16  g_ph[(size_t)NB * NH * NT * NT], g_pl[(size_t)NB * NH * NT * NT];
__device__ h16  g_ih[(size_t)NBT * NI], g_il[(size_t)NBT * NI];
#define WPL (4 * ND * ND + ND * NI + NI * ND)
#define WELEMS (NL * WPL + ND * NOUT)
__device__ h16  g_wh[WELEMS];

__device__ __forceinline__ uint32_t smem_u32(const void* p) {
    uint32_t a;
    asm("{ .reg .u64 t; cvta.to.shared.u64 t, %1; cvt.u32.u64 %0, t; }" : "=r"(a) : "l"(p));
    return a;
}
__device__ __forceinline__ float gelu_f(float x) {
    return 0.5f * x * (1.0f + erff(x * 0.7071067811865476f));
}
__device__ __forceinline__ void split2(float v, h16& h, h16& l) {
    h = __float2half_rn(v);
    l = __float2half_rn(v - __half2float(h));
}
__device__ __forceinline__ void ldsm4(uint32_t& r0, uint32_t& r1, uint32_t& r2, uint32_t& r3, uint32_t a) {
    asm volatile("ldmatrix.sync.aligned.m8n8.x4.shared.b16 {%0,%1,%2,%3}, [%4];"
                 : "=r"(r0), "=r"(r1), "=r"(r2), "=r"(r3) : "r"(a));
}
__device__ __forceinline__ void mma16816(float* c, const uint32_t* a, const uint32_t* b) {
    asm volatile("mma.sync.aligned.m16n8k16.row.col.f32.f16.f16.f32 "
                 "{%0,%1,%2,%3},{%4,%5,%6,%7},{%8,%9},{%0,%1,%2,%3};"
                 : "+f"(c[0]), "+f"(c[1]), "+f"(c[2]), "+f"(c[3])
                 : "r"(a[0]), "r"(a[1]), "r"(a[2]), "r"(a[3]), "r"(b[0]), "r"(b[1]));
}
__device__ __forceinline__ void cpasync16(uint32_t dst, const void* src) {
    asm volatile("cp.async.cg.shared.global [%0], [%1], 16;" :: "r"(dst), "l"(src));
}
__device__ __forceinline__ void cpcommit() { asm volatile("cp.async.commit_group;" ::: "memory"); }
template<int N> __device__ __forceinline__ void cpwait() {
    asm volatile("cp.async.wait_group %0;" :: "n"(N) : "memory");
}
__device__ __forceinline__ uint32_t swoff(int r, int c16) {
    return (uint32_t)(r * 128 + ((c16 ^ (r & 7)) * 16));
}

// ---------------- split-fp16 warp-MMA GEMM (2-term: AhBh + AlBh) ----------------
// D[128,BN] = act(alpha*((Ah+Al)[128,K] @ (Bh[BN,K])^T) + bias)
// OUTM: 0=fp32 C, 1=h16 hi/lo C, 2=h16 hi/lo transposed C. WLO: write Cl?
template<int BN, int ACT, int OUTM, bool WLO>
__global__ void __launch_bounds__(256) tgemm(
    const h16* __restrict__ Ah, const h16* __restrict__ Al,
    const h16* __restrict__ Bh,
    const float* __restrict__ bias, float alpha,
    float* __restrict__ Cf, h16* __restrict__ Ch, h16* __restrict__ Cl,
    int K, int lda, int ldb, int ldc,
    ll oA, ll iA, ll oB, ll iB, ll oC, ll iC, int h)
{
    constexpr int ABYTES = 128 * 128;
    constexpr int BBYTES = BN * 128;
    constexpr int STAGE  = 2 * ABYTES + BBYTES;
    constexpr int WN     = BN / 2;
    constexpr int NT8    = WN / 8;

    extern __shared__ __align__(128) char smem[];
    const uint32_t sb = smem_u32(smem);
    const int tid = threadIdx.x, lane = tid & 31, wid = tid >> 5;
    const int wm = wid >> 1, wn = wid & 1;

    const int z = blockIdx.z;
    const ll aoff = (ll)(z / h) * oA + (ll)(z % h) * iA;
    const ll boff = (ll)(z / h) * oB + (ll)(z % h) * iB;
    const ll coff = (ll)(z / h) * oC + (ll)(z % h) * iC;
    const int bm = blockIdx.y * 128;
    const int bn = blockIdx.x * BN;
    const h16* a0h = Ah + aoff + (ll)bm * lda;
    const h16* a0l = Al + aoff + (ll)bm * lda;
    const h16* b0h = Bh + boff + (ll)bn * ldb;

    float acc[2][NT8][4];
#pragma unroll
    for (int i = 0; i < 2; i++)
#pragma unroll
        for (int j = 0; j < NT8; j++)
#pragma unroll
            for (int t = 0; t < 4; t++) acc[i][j][t] = 0.0f;

    const int nch = K >> 6;

    const int aRow = (lane & 7) | (((lane >> 3) & 1) << 3);
    const int aC   = lane >> 4;
    const int bRow = (lane & 7) | (((lane >> 4) & 1) << 3);
    const int bC   = (lane >> 3) & 1;

    auto issue = [&](int c, int s) {
        const int k0 = c * 64;
        const uint32_t base = sb + s * STAGE;
        constexpr int TOT = (2 * 128 + BN) * 8;
#pragma unroll 4
        for (int u = tid; u < TOT; u += 256) {
            const int chunk = u & 7, row = u >> 3;
            const h16* src; uint32_t dbase; int r, ld;
            if (row < 128)       { src = a0h; r = row;       dbase = base;              ld = lda; }
            else if (row < 256)  { src = a0l; r = row - 128; dbase = base + ABYTES;     ld = lda; }
            else                 { src = b0h; r = row - 256; dbase = base + 2 * ABYTES; ld = ldb; }
            cpasync16(dbase + swoff(r, chunk), src + (ll)r * ld + k0 + chunk * 8);
        }
    };

    issue(0, 0);
    cpcommit();

    for (int c = 0; c < nch; c++) {
        if (c + 1 < nch) { issue(c + 1, (c + 1) & 1); cpcommit(); cpwait<1>(); }
        else             { cpwait<0>(); }
        __syncthreads();

        const uint32_t tAh = sb + (c & 1) * STAGE;
        const uint32_t tAl = tAh + ABYTES;
        const uint32_t tBh = tAh + 2 * ABYTES;

#pragma unroll
        for (int ks = 0; ks < 4; ks++) {
            uint32_t ah[2][4], al[2][4], bh[NT8][2];
#pragma unroll
            for (int mt = 0; mt < 2; mt++) {
                const int r = wm * 32 + mt * 16 + aRow;
                const int c16 = ks * 2 + aC;
                ldsm4(ah[mt][0], ah[mt][1], ah[mt][2], ah[mt][3], tAh + swoff(r, c16));
                ldsm4(al[mt][0], al[mt][1], al[mt][2], al[mt][3], tAl + swoff(r, c16));
            }
#pragma unroll
            for (int nt2 = 0; nt2 < NT8 / 2; nt2++) {
                const int r = wn * WN + nt2 * 16 + bRow;
                const int c16 = ks * 2 + bC;
                ldsm4(bh[2*nt2][0], bh[2*nt2][1], bh[2*nt2+1][0], bh[2*nt2+1][1], tBh + swoff(r, c16));
            }
#pragma unroll
            for (int mt = 0; mt < 2; mt++)
#pragma unroll
                for (int nt = 0; nt < NT8; nt++) {
                    mma16816(acc[mt][nt], ah[mt], bh[nt]);
                    mma16816(acc[mt][nt], al[mt], bh[nt]);
                }
        }
        __syncthreads();
    }

    const int gid = lane >> 2, tig2 = (lane & 3) * 2;
#pragma unroll
    for (int mt = 0; mt < 2; mt++) {
#pragma unroll
        for (int nt = 0; nt < NT8; nt++) {
            const int n = bn + wn * WN + nt * 8 + tig2;
            float bv0 = 0.f, bv1 = 0.f;
            if (bias) { bv0 = bias[n]; bv1 = bias[n + 1]; }
#pragma unroll
            for (int hf = 0; hf < 2; hf++) {
                const int m = bm + wm * 32 + mt * 16 + gid + hf * 8;
                float v0 = acc[mt][nt][hf * 2]     * alpha + bv0;
                float v1 = acc[mt][nt][hf * 2 + 1] * alpha + bv1;
                if (ACT) { v0 = gelu_f(v0); v1 = gelu_f(v1); }
                if (OUTM == 0) {
                    *reinterpret_cast<float2*>(Cf + coff + (ll)m * ldc + n) = make_float2(v0, v1);
                } else if (OUTM == 1) {
                    h16 h0, l0, h1, l1;
                    split2(v0, h0, l0); split2(v1, h1, l1);
                    *reinterpret_cast<__half2*>(Ch + coff + (ll)m * ldc + n) = __halves2half2(h0, h1);
                    if (WLO)
                        *reinterpret_cast<__half2*>(Cl + coff + (ll)m * ldc + n) = __halves2half2(l0, l1);
                } else {
                    h16 h0, l0, h1, l1;
                    split2(v0, h0, l0); split2(v1, h1, l1);
                    Ch[coff + (ll)n * ldc + m] = h0;
                    Ch[coff + (ll)(n + 1) * ldc + m] = h1;
                    if (WLO) {
                        Cl[coff + (ll)n * ldc + m] = l0;
                        Cl[coff + (ll)(n + 1) * ldc + m] = l1;
                    }
                }
            }
        }
    }
}

// W[K,N] -> Th[N,K] (hi only)
__global__ void __launch_bounds__(256) wsplit_kernel(const float* __restrict__ W,
                                                     h16* __restrict__ Th, int K, int N) {
    __shared__ float t[32][33];
    const int n0 = blockIdx.x * 32, k0 = blockIdx.y * 32;
    const int tx = threadIdx.x, ty = threadIdx.y;
#pragma unroll
    for (int i = 0; i < 4; i++)
        t[ty + i * 8][tx] = W[(ll)(k0 + ty + i * 8) * N + n0 + tx];
    __syncthreads();
#pragma unroll
    for (int i = 0; i < 4; i++) {
        int n = ty + i * 8;
        Th[(ll)(n0 + n) * K + k0 + tx] = __float2half_rn(t[tx][n]);
    }
}

__global__ void concat_kernel(const float* __restrict__ hs, const float* __restrict__ mem) {
    int i4 = blockIdx.x * blockDim.x + threadIdx.x;
    if (i4 >= NBT * ND / 4) return;
    int idx = i4 * 4;
    int d = idx % ND;
    int t = (idx / ND) % NT;
    int b = idx / (ND * NT);
    float4 v = (t < NM) ? *reinterpret_cast<const float4*>(mem + t * ND + d)
                        : *reinterpret_cast<const float4*>(hs + ((size_t)(b * NS + t - NM)) * ND + d);
    *reinterpret_cast<float4*>(g_x + idx) = v;
    h16 H[4], L[4];
    split2(v.x, H[0], L[0]); split2(v.y, H[1], L[1]);
    split2(v.z, H[2], L[2]); split2(v.w, H[3], L[3]);
    *reinterpret_cast<__half2*>(g_xh + idx)     = __halves2half2(H[0], H[1]);
    *reinterpret_cast<__half2*>(g_xh + idx + 2) = __halves2half2(H[2], H[3]);
    *reinterpret_cast<__half2*>(g_xl + idx)     = __halves2half2(L[0], L[1]);
    *reinterpret_cast<__half2*>(g_xl + idx + 2) = __halves2half2(L[2], L[3]);
}

__global__ void __launch_bounds__(256) softmax_kernel() {
    const size_t ro = (size_t)blockIdx.x * NT;
    __shared__ float red[8];
    __shared__ float sv;
    const int tid = threadIdx.x;
    float4 v = *reinterpret_cast<const float4*>(g_scores + ro + tid * 4);
    float mx = fmaxf(fmaxf(v.x, v.y), fmaxf(v.z, v.w));
    for (int o = 16; o > 0; o >>= 1) mx = fmaxf(mx, __shfl_xor_sync(0xffffffffu, mx, o));
    if ((tid & 31) == 0) red[tid >> 5] = mx;
    __syncthreads();
    if (tid == 0) { float m = red[0]; for (int i = 1; i < 8; i++) m = fmaxf(m, red[i]); sv = m; }
    __syncthreads();
    const float m = sv;
    v.x = expf(v.x - m); v.y = expf(v.y - m); v.z = expf(v.z - m); v.w = expf(v.w - m);
    float s = v.x + v.y + v.z + v.w;
    for (int o = 16; o > 0; o >>= 1) s += __shfl_xor_sync(0xffffffffu, s, o);
    if ((tid & 31) == 0) red[tid >> 5] = s;
    __syncthreads();
    if (tid == 0) { float t = 0; for (int i = 0; i < 8; i++) t += red[i]; sv = 1.0f / t; }
    __syncthreads();
    const float inv = sv;
    h16 H[4], L[4];
    split2(v.x * inv, H[0], L[0]); split2(v.y * inv, H[1], L[1]);
    split2(v.z * inv, H[2], L[2]); split2(v.w * inv, H[3], L[3]);
    *reinterpret_cast<__half2*>(g_ph + ro + tid * 4)     = __halves2half2(H[0], H[1]);
    *reinterpret_cast<__half2*>(g_ph + ro + tid * 4 + 2) = __halves2half2(H[2], H[3]);
    *reinterpret_cast<__half2*>(g_pl + ro + tid * 4)     = __halves2half2(L[0], L[1]);
    *reinterpret_cast<__half2*>(g_pl + ro + tid * 4 + 2) = __halves2half2(L[2], L[3]);
}

__global__ void __launch_bounds__(256) add_ln_kernel(const float* __restrict__ y,
                                                     const float* __restrict__ gam,
                                                     const float* __restrict__ bet) {
    __shared__ float red[8];
    __shared__ float s0, s1;
    const int tid = threadIdx.x;
    const size_t base = (size_t)blockIdx.x * ND;
    const int c = tid * 4;
    float4 a = *reinterpret_cast<const float4*>(y + base + c);
    float4 xo = *reinterpret_cast<const float4*>(g_x + base + c);
    float v0 = a.x + xo.x, v1 = a.y + xo.y, v2 = a.z + xo.z, v3 = a.w + xo.w;
    float s = v0 + v1 + v2 + v3;
    for (int o = 16; o > 0; o >>= 1) s += __shfl_xor_sync(0xffffffffu, s, o);
    if ((tid & 31) == 0) red[tid >> 5] = s;
    __syncthreads();
    if (tid == 0) { float t = 0; for (int i = 0; i < 8; i++) t += red[i]; s0 = t * (1.0f / ND); }
    __syncthreads();
    const float mean = s0;
    float d0 = v0 - mean, d1 = v1 - mean, d2 = v2 - mean, d3 = v3 - mean;
    float vs = d0*d0 + d1*d1 + d2*d2 + d3*d3;
    for (int o = 16; o > 0; o >>= 1) vs += __shfl_xor_sync(0xffffffffu, vs, o);
    if ((tid & 31) == 0) red[tid >> 5] = vs;
    __syncthreads();
    if (tid == 0) { float t = 0; for (int i = 0; i < 8; i++) t += red[i]; s1 = rsqrtf(t * (1.0f / ND) + 1e-12f); }
    __syncthreads();
    const float inv = s1;
    float4 gv = *reinterpret_cast<const float4*>(gam + c);
    float4 bv = *reinterpret_cast<const float4*>(bet + c);
    float r0 = d0*inv*gv.x + bv.x, r1 = d1*inv*gv.y + bv.y;
    float r2 = d2*inv*gv.z + bv.z, r3 = d3*inv*gv.w + bv.w;
    *reinterpret_cast<float4*>(g_x + base + c) = make_float4(r0, r1, r2, r3);
    h16 H[4], L[4];
    split2(r0, H[0], L[0]); split2(r1, H[1], L[1]);
    split2(r2, H[2], L[2]); split2(r3, H[3], L[3]);
    *reinterpret_cast<__half2*>(g_xh + base + c)     = __halves2half2(H[0], H[1]);
    *reinterpret_cast<__half2*>(g_xh + base + c + 2) = __halves2half2(H[2], H[3]);
    *reinterpret_cast<__half2*>(g_xl + base + c)     = __halves2half2(L[0], L[1]);
    *reinterpret_cast<__half2*>(g_xl + base + c + 2) = __halves2half2(L[2], L[3]);
}

__global__ void readout_kernel(float* __restrict__ out) {
    int idx = blockIdx.x * blockDim.x + threadIdx.x;
    if (idx >= NB * NM * ND) return;
    int d = idx % ND;
    int t = (idx / ND) % NM;
    int b = idx / (ND * NM);
    out[(size_t)NB * NS * NOUT + idx] = g_x[((size_t)b * NT + t) * ND + d];
}

#define S128 (2 * (2 * 128 * 128 + 128 * 128))   // 98304
#define S64  (2 * (2 * 128 * 128 + 64 * 128))    // 81920

extern "C" void kernel_launch(void* const* d_in, const int* in_sizes, int n_in,
                              void* d_out, int out_size) {
    const float* hs   = (const float*)d_in[0];
    const float* mem  = (const float*)d_in[1];
    const float* Wq   = (const float*)d_in[2];
    const float* bq   = (const float*)d_in[3];
    const float* Wk   = (const float*)d_in[4];
    const float* bk   = (const float*)d_in[5];
    const float* Wv   = (const float*)d_in[6];
    const float* bv   = (const float*)d_in[7];
    const float* Wo   = (const float*)d_in[8];
    const float* bo   = (const float*)d_in[9];
    const float* ln1g = (const float*)d_in[10];
    const float* ln1b = (const float*)d_in[11];
    const float* Wm   = (const float*)d_in[12];
    const float* bmv  = (const float*)d_in[13];
    const float* Wr   = (const float*)d_in[14];
    const float* br   = (const float*)d_in[15];
    const float* ln2g = (const float*)d_in[16];
    const float* ln2b = (const float*)d_in[17];
    const float* Wp   = (const float*)d_in[18];
    const float* bp   = (const float*)d_in[19];
    float* out = (float*)d_out;

    static h16 *wh = nullptr, *xh, *xl, *qh, *ql, *kh;
    static h16 *vth, *t0h, *t0l, *ph, *pl, *ih, *il;
    static float *px, *py, *psc;
    if (!wh) {
        cudaGetSymbolAddress((void**)&wh, g_wh);
        cudaGetSymbolAddress((void**)&xh, g_xh);   cudaGetSymbolAddress((void**)&xl, g_xl);
        cudaGetSymbolAddress((void**)&qh, g_qh);   cudaGetSymbolAddress((void**)&ql, g_ql);
        cudaGetSymbolAddress((void**)&kh, g_kh);
        cudaGetSymbolAddress((void**)&vth, g_vth);
        cudaGetSymbolAddress((void**)&t0h, g_t0h); cudaGetSymbolAddress((void**)&t0l, g_t0l);
        cudaGetSymbolAddress((void**)&ph, g_ph);   cudaGetSymbolAddress((void**)&pl, g_pl);
        cudaGetSymbolAddress((void**)&ih, g_ih);   cudaGetSymbolAddress((void**)&il, g_il);
        cudaGetSymbolAddress((void**)&px, g_x);    cudaGetSymbolAddress((void**)&py, g_y);
        cudaGetSymbolAddress((void**)&psc, g_scores);
        cudaFuncSetAttribute((const void*)tgemm<128,0,0,false>, cudaFuncAttributeMaxDynamicSharedMemorySize, S128);
        cudaFuncSetAttribute((const void*)tgemm<128,0,1,true>,  cudaFuncAttributeMaxDynamicSharedMemorySize, S128);
        cudaFuncSetAttribute((const void*)tgemm<128,0,1,false>, cudaFuncAttributeMaxDynamicSharedMemorySize, S128);
        cudaFuncSetAttribute((const void*)tgemm<128,0,2,false>, cudaFuncAttributeMaxDynamicSharedMemorySize, S128);
        cudaFuncSetAttribute((const void*)tgemm<64,0,1,true>,   cudaFuncAttributeMaxDynamicSharedMemorySize, S64);
        cudaFuncSetAttribute((const void*)tgemm<128,1,1,true>,  cudaFuncAttributeMaxDynamicSharedMemorySize, S128);
        cudaFuncSetAttribute((const void*)tgemm<128,1,0,false>, cudaFuncAttributeMaxDynamicSharedMemorySize, S128);
    }

    const ll Z = 0;
    const ll DD = (ll)ND * ND;
    dim3 t32(32, 8);

    for (int l = 0; l < NL; l++) {
        ll o = (ll)l * WPL;
        wsplit_kernel<<<dim3(ND/32, ND/32), t32>>>(Wq + l*DD, wh + o,        ND, ND);
        wsplit_kernel<<<dim3(ND/32, ND/32), t32>>>(Wk + l*DD, wh + o + DD,   ND, ND);
        wsplit_kernel<<<dim3(ND/32, ND/32), t32>>>(Wv + l*DD, wh + o + 2*DD, ND, ND);
        wsplit_kernel<<<dim3(ND/32, ND/32), t32>>>(Wo + l*DD, wh + o + 3*DD, ND, ND);
        wsplit_kernel<<<dim3(NI/32, ND/32), t32>>>(Wm + (ll)l*ND*NI, wh + o + 4*DD, ND, NI);
        wsplit_kernel<<<dim3(ND/32, NI/32), t32>>>(Wr + (ll)l*NI*ND, wh + o + 4*DD + (ll)ND*NI, NI, ND);
    }
    wsplit_kernel<<<dim3(NOUT/32, ND/32), t32>>>(Wp, wh + (ll)NL*WPL, ND, NOUT);

    concat_kernel<<<(NBT * ND / 4 + 255) / 256, 256>>>(hs, mem);

    for (int l = 0; l < NL; l++) {
        ll o = (ll)l * WPL;
        const h16 *wqh = wh + o;
        const h16 *wkh = wh + o + DD;
        const h16 *wvh = wh + o + 2*DD;
        const h16 *woh = wh + o + 3*DD;
        const h16 *wmh = wh + o + 4*DD;
        const h16 *wrh = wh + o + 4*DD + (ll)ND*NI;

        tgemm<128,0,1,true><<<dim3(8, 32, 1), 256, S128>>>(xh, xl, wqh, bq + l*ND, 1.f,
            nullptr, qh, ql, ND, ND, ND, ND, Z,Z,Z,Z,Z,Z, 1);
        tgemm<128,0,1,false><<<dim3(8, 32, 1), 256, S128>>>(xh, xl, wkh, bk + l*ND, 1.f,
            nullptr, kh, nullptr, ND, ND, ND, ND, Z,Z,Z,Z,Z,Z, 1);
        tgemm<128,0,2,false><<<dim3(8, 32, 1), 256, S128>>>(xh, xl, wvh, bv + l*ND, 1.f,
            nullptr, vth, nullptr, ND, ND, ND, NBT, Z,Z,Z,Z,Z,Z, 1);

        tgemm<128,0,0,false><<<dim3(8, 8, NB*NH), 256, S128>>>(qh, ql, kh, nullptr, 0.125f,
            psc, nullptr, nullptr, NDH, ND, ND, NT,
            (ll)NT*ND, (ll)NDH, (ll)NT*ND, (ll)NDH, (ll)NH*NT*NT, (ll)NT*NT, NH);

        softmax_kernel<<<NB*NH*NT, 256>>>();

        tgemm<64,0,1,true><<<dim3(1, 8, NB*NH), 256, S64>>>(ph, pl, vth, nullptr, 1.f,
            nullptr, t0h, t0l, NT, NT, NBT, ND,
            (ll)NH*NT*NT, (ll)NT*NT, (ll)NT, (ll)NDH*NBT, (ll)NT*ND, (ll)NDH, NH);

        tgemm<128,0,0,false><<<dim3(8, 32, 1), 256, S128>>>(t0h, t0l, woh, bo + l*ND, 1.f,
            py, nullptr, nullptr, ND, ND, ND, ND, Z,Z,Z,Z,Z,Z, 1);
        add_ln_kernel<<<NBT, 256>>>(py, ln1g + l*ND, ln1b + l*ND);

        tgemm<128,1,1,true><<<dim3(32, 32, 1), 256, S128>>>(xh, xl, wmh, bmv + l*NI, 1.f,
            nullptr, ih, il, ND, ND, ND, NI, Z,Z,Z,Z,Z,Z, 1);
        tgemm<128,0,0,false><<<dim3(8, 32, 1), 256, S128>>>(ih, il, wrh, br + l*ND, 1.f,
            py, nullptr, nullptr, NI, NI, NI, ND, Z,Z,Z,Z,Z,Z, 1);
        add_ln_kernel<<<NBT, 256>>>(py, ln2g + l*ND, ln2b + l*ND);
    }

    tgemm<128,1,0,false><<<dim3(32, 7, NB), 256, S128>>>(xh + NM*ND, xl + NM*ND,
        wh + (ll)NL*WPL, bp, 1.f,
        out, nullptr, nullptr, ND, ND, ND, NOUT,
        (ll)NT*ND, Z, Z, Z, (ll)NS*NOUT, Z, 1);

    readout_kernel<<<(NB * NM * ND + 255) / 256, 256>>>(out);
}

// round 6
// speedup vs baseline: 3.6542x; 1.0629x over previous
#include <cuda_runtime.h>
#include <cuda_fp16.h>
#include <math.h>
#include <stdint.h>

#define NB   4
#define NS   896
#define ND   1024
#define NH   16
#define NDH  64
#define NI   4096
#define NOUT 4096
#define NL   2
#define NM   128
#define NT   1024
#define NBT  4096

typedef __half h16;
typedef long long ll;

__device__ float g_x[NBT * ND];
__device__ float g_y[NBT * ND];
__device__ float g_scores[(size_t)NB * NH * NT * NT];
__device__ h16  g_xh[NBT * ND],  g_xl[NBT * ND];
__device__ h16  g_qh[NBT * ND],  g_ql[NBT * ND];
__device__ h16  g_kh[NBT * ND];
__device__ h16  g_vth[NBT * ND];
__device__ h16  g_t0h[NBT * ND], g_t0l[NBT * ND];
__device__ h16  g_ph[(size_t)NB * NH * NT * NT], g_pl[(size_t)NB * NH * NT * NT];
__device__ h16  g_ih[(size_t)NBT * NI], g_il[(size_t)NBT * NI];
#define WPL (4 * ND * ND + ND * NI + NI * ND)
#define WELEMS (NL * WPL + ND * NOUT)
__device__ h16  g_wh[WELEMS];

__device__ __forceinline__ uint32_t smem_u32(const void* p) {
    uint32_t a;
    asm("{ .reg .u64 t; cvta.to.shared.u64 t, %1; cvt.u32.u64 %0, t; }" : "=r"(a) : "l"(p));
    return a;
}
__device__ __forceinline__ float gelu_f(float x) {
    return 0.5f * x * (1.0f + erff(x * 0.7071067811865476f));
}
__device__ __forceinline__ void split2(float v, h16& h, h16& l) {
    h = __float2half_rn(v);
    l = __float2half_rn(v - __half2float(h));
}
__device__ __forceinline__ void ldsm4(uint32_t& r0, uint32_t& r1, uint32_t& r2, uint32_t& r3, uint32_t a) {
    asm volatile("ldmatrix.sync.aligned.m8n8.x4.shared.b16 {%0,%1,%2,%3}, [%4];"
                 : "=r"(r0), "=r"(r1), "=r"(r2), "=r"(r3) : "r"(a));
}
__device__ __forceinline__ void mma16816(float* c, const uint32_t* a, const uint32_t* b) {
    asm volatile("mma.sync.aligned.m16n8k16.row.col.f32.f16.f16.f32 "
                 "{%0,%1,%2,%3},{%4,%5,%6,%7},{%8,%9},{%0,%1,%2,%3};"
                 : "+f"(c[0]), "+f"(c[1]), "+f"(c[2]), "+f"(c[3])
                 : "r"(a[0]), "r"(a[1]), "r"(a[2]), "r"(a[3]), "r"(b[0]), "r"(b[1]));
}
__device__ __forceinline__ void cpasync16(uint32_t dst, const void* src) {
    asm volatile("cp.async.cg.shared.global [%0], [%1], 16;" :: "r"(dst), "l"(src));
}
__device__ __forceinline__ void cpcommit() { asm volatile("cp.async.commit_group;" ::: "memory"); }
template<int N> __device__ __forceinline__ void cpwait() {
    asm volatile("cp.async.wait_group %0;" :: "n"(N) : "memory");
}
__device__ __forceinline__ uint32_t swoff(int r, int c16) {
    return (uint32_t)(r * 128 + ((c16 ^ (r & 7)) * 16));
}

// ---------------- split-fp16 warp-MMA GEMM (2-term: AhBh + AlBh) ----------------
// D[128,BN] = act(alpha*((Ah+Al)[128,K] @ (Bh[BN,K])^T) + bias)
// OUTM: 0=fp32 C, 1=h16 hi/lo C, 2=h16 hi transposed C (smem-staged). WLO: write Cl?
template<int BN, int ACT, int OUTM, bool WLO>
__global__ void __launch_bounds__(256, 2) tgemm(
    const h16* __restrict__ Ah, const h16* __restrict__ Al,
    const h16* __restrict__ Bh,
    const float* __restrict__ bias, float alpha,
    float* __restrict__ Cf, h16* __restrict__ Ch, h16* __restrict__ Cl,
    int K, int lda, int ldb, int ldc,
    ll oA, ll iA, ll oB, ll iB, ll oC, ll iC, int h)
{
    constexpr int ABYTES = 128 * 128;
    constexpr int BBYTES = BN * 128;
    constexpr int STAGE  = 2 * ABYTES + BBYTES;
    constexpr int WN     = BN / 2;
    constexpr int NT8    = WN / 8;

    extern __shared__ __align__(128) char smem[];
    const uint32_t sb = smem_u32(smem);
    const int tid = threadIdx.x, lane = tid & 31, wid = tid >> 5;
    const int wm = wid >> 1, wn = wid & 1;

    const int z = blockIdx.z;
    const ll aoff = (ll)(z / h) * oA + (ll)(z % h) * iA;
    const ll boff = (ll)(z / h) * oB + (ll)(z % h) * iB;
    const ll coff = (ll)(z / h) * oC + (ll)(z % h) * iC;
    const int bm = blockIdx.y * 128;
    const int bn = blockIdx.x * BN;
    const h16* a0h = Ah + aoff + (ll)bm * lda;
    const h16* a0l = Al + aoff + (ll)bm * lda;
    const h16* b0h = Bh + boff + (ll)bn * ldb;

    float acc[2][NT8][4];
#pragma unroll
    for (int i = 0; i < 2; i++)
#pragma unroll
        for (int j = 0; j < NT8; j++)
#pragma unroll
            for (int t = 0; t < 4; t++) acc[i][j][t] = 0.0f;

    const int nch = K >> 6;

    const int aRow = (lane & 7) | (((lane >> 3) & 1) << 3);
    const int aC   = lane >> 4;
    const int bRow = (lane & 7) | (((lane >> 4) & 1) << 3);
    const int bC   = (lane >> 3) & 1;

    auto issue = [&](int c, int s) {
        const int k0 = c * 64;
        const uint32_t base = sb + s * STAGE;
        constexpr int TOT = (2 * 128 + BN) * 8;
#pragma unroll 4
        for (int u = tid; u < TOT; u += 256) {
            const int chunk = u & 7, row = u >> 3;
            const h16* src; uint32_t dbase; int r, ld;
            if (row < 128)       { src = a0h; r = row;       dbase = base;              ld = lda; }
            else if (row < 256)  { src = a0l; r = row - 128; dbase = base + ABYTES;     ld = lda; }
            else                 { src = b0h; r = row - 256; dbase = base + 2 * ABYTES; ld = ldb; }
            cpasync16(dbase + swoff(r, chunk), src + (ll)r * ld + k0 + chunk * 8);
        }
    };

    issue(0, 0);
    cpcommit();

    for (int c = 0; c < nch; c++) {
        if (c + 1 < nch) { issue(c + 1, (c + 1) & 1); cpcommit(); cpwait<1>(); }
        else             { cpwait<0>(); }
        __syncthreads();

        const uint32_t tAh = sb + (c & 1) * STAGE;
        const uint32_t tAl = tAh + ABYTES;
        const uint32_t tBh = tAh + 2 * ABYTES;

#pragma unroll
        for (int ks = 0; ks < 4; ks++) {
            uint32_t ah[2][4], al[2][4], bh[NT8][2];
#pragma unroll
            for (int mt = 0; mt < 2; mt++) {
                const int r = wm * 32 + mt * 16 + aRow;
                const int c16 = ks * 2 + aC;
                ldsm4(ah[mt][0], ah[mt][1], ah[mt][2], ah[mt][3], tAh + swoff(r, c16));
                ldsm4(al[mt][0], al[mt][1], al[mt][2], al[mt][3], tAl + swoff(r, c16));
            }
#pragma unroll
            for (int nt2 = 0; nt2 < NT8 / 2; nt2++) {
                const int r = wn * WN + nt2 * 16 + bRow;
                const int c16 = ks * 2 + bC;
                ldsm4(bh[2*nt2][0], bh[2*nt2][1], bh[2*nt2+1][0], bh[2*nt2+1][1], tBh + swoff(r, c16));
            }
#pragma unroll
            for (int mt = 0; mt < 2; mt++)
#pragma unroll
                for (int nt = 0; nt < NT8; nt++) {
                    mma16816(acc[mt][nt], ah[mt], bh[nt]);
                    mma16816(acc[mt][nt], al[mt], bh[nt]);
                }
        }
        __syncthreads();
    }

    const int gid = lane >> 2, tig2 = (lane & 3) * 2;

    if (OUTM == 2) {
        // stage transposed tile in smem: [n_local][m_local], row stride 272B
        constexpr int TSTRIDE = 272;
#pragma unroll
        for (int mt = 0; mt < 2; mt++)
#pragma unroll
            for (int nt = 0; nt < NT8; nt++) {
                const int nl = wn * WN + nt * 8 + tig2;
#pragma unroll
                for (int hf = 0; hf < 2; hf++) {
                    const int ml = wm * 32 + mt * 16 + gid + hf * 8;
                    h16 h0 = __float2half_rn(acc[mt][nt][hf * 2]     * alpha);
                    h16 h1 = __float2half_rn(acc[mt][nt][hf * 2 + 1] * alpha);
                    *reinterpret_cast<h16*>(smem + nl * TSTRIDE + ml * 2) = h0;
                    *reinterpret_cast<h16*>(smem + (nl + 1) * TSTRIDE + ml * 2) = h1;
                }
            }
        __syncthreads();
        // coalesced copy-out: BN rows of 128 h16 (bias along n, added scalar)
        for (int u = tid; u < BN * 16; u += 256) {
            const int nl = u >> 4, c16 = (u & 15) * 8;
            uint4 v = *reinterpret_cast<const uint4*>(smem + nl * TSTRIDE + c16 * 2);
            if (bias) {
                h16* hv = reinterpret_cast<h16*>(&v);
                const float bb = bias[bn + nl];
#pragma unroll
                for (int t = 0; t < 8; t++) hv[t] = __float2half_rn(__half2float(hv[t]) + bb);
            }
            *reinterpret_cast<uint4*>(Ch + coff + (ll)(bn + nl) * ldc + bm + c16) = v;
        }
        return;
    }

#pragma unroll
    for (int mt = 0; mt < 2; mt++) {
#pragma unroll
        for (int nt = 0; nt < NT8; nt++) {
            const int n = bn + wn * WN + nt * 8 + tig2;
            float bv0 = 0.f, bv1 = 0.f;
            if (bias) { bv0 = bias[n]; bv1 = bias[n + 1]; }
#pragma unroll
            for (int hf = 0; hf < 2; hf++) {
                const int m = bm + wm * 32 + mt * 16 + gid + hf * 8;
                float v0 = acc[mt][nt][hf * 2]     * alpha + bv0;
                float v1 = acc[mt][nt][hf * 2 + 1] * alpha + bv1;
                if (ACT) { v0 = gelu_f(v0); v1 = gelu_f(v1); }
                if (OUTM == 0) {
                    *reinterpret_cast<float2*>(Cf + coff + (ll)m * ldc + n) = make_float2(v0, v1);
                } else {
                    h16 h0, l0, h1, l1;
                    split2(v0, h0, l0); split2(v1, h1, l1);
                    *reinterpret_cast<__half2*>(Ch + coff + (ll)m * ldc + n) = __halves2half2(h0, h1);
                    if (WLO)
                        *reinterpret_cast<__half2*>(Cl + coff + (ll)m * ldc + n) = __halves2half2(l0, l1);
                }
            }
        }
    }
}

// W[K,N] -> Th[N,K] (hi only)
__global__ void __launch_bounds__(256) wsplit_kernel(const float* __restrict__ W,
                                                     h16* __restrict__ Th, int K, int N) {
    __shared__ float t[32][33];
    const int n0 = blockIdx.x * 32, k0 = blockIdx.y * 32;
    const int tx = threadIdx.x, ty = threadIdx.y;
#pragma unroll
    for (int i = 0; i < 4; i++)
        t[ty + i * 8][tx] = W[(ll)(k0 + ty + i * 8) * N + n0 + tx];
    __syncthreads();
#pragma unroll
    for (int i = 0; i < 4; i++) {
        int n = ty + i * 8;
        Th[(ll)(n0 + n) * K + k0 + tx] = __float2half_rn(t[tx][n]);
    }
}

__global__ void concat_kernel(const float* __restrict__ hs, const float* __restrict__ mem) {
    int i4 = blockIdx.x * blockDim.x + threadIdx.x;
    if (i4 >= NBT * ND / 4) return;
    int idx = i4 * 4;
    int d = idx % ND;
    int t = (idx / ND) % NT;
    int b = idx / (ND * NT);
    float4 v = (t < NM) ? *reinterpret_cast<const float4*>(mem + t * ND + d)
                        : *reinterpret_cast<const float4*>(hs + ((size_t)(b * NS + t - NM)) * ND + d);
    *reinterpret_cast<float4*>(g_x + idx) = v;
    h16 H[4], L[4];
    split2(v.x, H[0], L[0]); split2(v.y, H[1], L[1]);
    split2(v.z, H[2], L[2]); split2(v.w, H[3], L[3]);
    *reinterpret_cast<__half2*>(g_xh + idx)     = __halves2half2(H[0], H[1]);
    *reinterpret_cast<__half2*>(g_xh + idx + 2) = __halves2half2(H[2], H[3]);
    *reinterpret_cast<__half2*>(g_xl + idx)     = __halves2half2(L[0], L[1]);
    *reinterpret_cast<__half2*>(g_xl + idx + 2) = __halves2half2(L[2], L[3]);
}

__global__ void __launch_bounds__(256) softmax_kernel() {
    const size_t ro = (size_t)blockIdx.x * NT;
    __shared__ float red[8];
    __shared__ float sv;
    const int tid = threadIdx.x;
    float4 v = *reinterpret_cast<const float4*>(g_scores + ro + tid * 4);
    float mx = fmaxf(fmaxf(v.x, v.y), fmaxf(v.z, v.w));
    for (int o = 16; o > 0; o >>= 1) mx = fmaxf(mx, __shfl_xor_sync(0xffffffffu, mx, o));
    if ((tid & 31) == 0) red[tid >> 5] = mx;
    __syncthreads();
    if (tid == 0) { float m = red[0]; for (int i = 1; i < 8; i++) m = fmaxf(m, red[i]); sv = m; }
    __syncthreads();
    const float m = sv;
    v.x = __expf(v.x - m); v.y = __expf(v.y - m); v.z = __expf(v.z - m); v.w = __expf(v.w - m);
    float s = v.x + v.y + v.z + v.w;
    for (int o = 16; o > 0; o >>= 1) s += __shfl_xor_sync(0xffffffffu, s, o);
    if ((tid & 31) == 0) red[tid >> 5] = s;
    __syncthreads();
    if (tid == 0) { float t = 0; for (int i = 0; i < 8; i++) t += red[i]; sv = 1.0f / t; }
    __syncthreads();
    const float inv = sv;
    h16 H[4], L[4];
    split2(v.x * inv, H[0], L[0]); split2(v.y * inv, H[1], L[1]);
    split2(v.z * inv, H[2], L[2]); split2(v.w * inv, H[3], L[3]);
    *reinterpret_cast<__half2*>(g_ph + ro + tid * 4)     = __halves2half2(H[0], H[1]);
    *reinterpret_cast<__half2*>(g_ph + ro + tid * 4 + 2) = __halves2half2(H[2], H[3]);
    *reinterpret_cast<__half2*>(g_pl + ro + tid * 4)     = __halves2half2(L[0], L[1]);
    *reinterpret_cast<__half2*>(g_pl + ro + tid * 4 + 2) = __halves2half2(L[2], L[3]);
}

__global__ void __launch_bounds__(256) add_ln_kernel(const float* __restrict__ y,
                                                     const float* __restrict__ gam,
                                                     const float* __restrict__ bet) {
    __shared__ float red[8];
    __shared__ float s0, s1;
    const int tid = threadIdx.x;
    const size_t base = (size_t)blockIdx.x * ND;
    const int c = tid * 4;
    float4 a = *reinterpret_cast<const float4*>(y + base + c);
    float4 xo = *reinterpret_cast<const float4*>(g_x + base + c);
    float v0 = a.x + xo.x, v1 = a.y + xo.y, v2 = a.z + xo.z, v3 = a.w + xo.w;
    float s = v0 + v1 + v2 + v3;
    for (int o = 16; o > 0; o >>= 1) s += __shfl_xor_sync(0xffffffffu, s, o);
    if ((tid & 31) == 0) red[tid >> 5] = s;
    __syncthreads();
    if (tid == 0) { float t = 0; for (int i = 0; i < 8; i++) t += red[i]; s0 = t * (1.0f / ND); }
    __syncthreads();
    const float mean = s0;
    float d0 = v0 - mean, d1 = v1 - mean, d2 = v2 - mean, d3 = v3 - mean;
    float vs = d0*d0 + d1*d1 + d2*d2 + d3*d3;
    for (int o = 16; o > 0; o >>= 1) vs += __shfl_xor_sync(0xffffffffu, vs, o);
    if ((tid & 31) == 0) red[tid >> 5] = vs;
    __syncthreads();
    if (tid == 0) { float t = 0; for (int i = 0; i < 8; i++) t += red[i]; s1 = rsqrtf(t * (1.0f / ND) + 1e-12f); }
    __syncthreads();
    const float inv = s1;
    float4 gv = *reinterpret_cast<const float4*>(gam + c);
    float4 bv = *reinterpret_cast<const float4*>(bet + c);
    float r0 = d0*inv*gv.x + bv.x, r1 = d1*inv*gv.y + bv.y;
    float r2 = d2*inv*gv.z + bv.z, r3 = d3*inv*gv.w + bv.w;
    *reinterpret_cast<float4*>(g_x + base + c) = make_float4(r0, r1, r2, r3);
    h16 H[4], L[4];
    split2(r0, H[0], L[0]); split2(r1, H[1], L[1]);
    split2(r2, H[2], L[2]); split2(r3, H[3], L[3]);
    *reinterpret_cast<__half2*>(g_xh + base + c)     = __halves2half2(H[0], H[1]);
    *reinterpret_cast<__half2*>(g_xh + base + c + 2) = __halves2half2(H[2], H[3]);
    *reinterpret_cast<__half2*>(g_xl + base + c)     = __halves2half2(L[0], L[1]);
    *reinterpret_cast<__half2*>(g_xl + base + c + 2) = __halves2half2(L[2], L[3]);
}

__global__ void readout_kernel(float* __restrict__ out) {
    int idx = blockIdx.x * blockDim.x + threadIdx.x;
    if (idx >= NB * NM * ND) return;
    int d = idx % ND;
    int t = (idx / ND) % NM;
    int b = idx / (ND * NM);
    out[(size_t)NB * NS * NOUT + idx] = g_x[((size_t)b * NT + t) * ND + d];
}

#define S128 (2 * (2 * 128 * 128 + 128 * 128))   // 98304
#define S64  (2 * (2 * 128 * 128 + 64 * 128))    // 81920

extern "C" void kernel_launch(void* const* d_in, const int* in_sizes, int n_in,
                              void* d_out, int out_size) {
    const float* hs   = (const float*)d_in[0];
    const float* mem  = (const float*)d_in[1];
    const float* Wq   = (const float*)d_in[2];
    const float* bq   = (const float*)d_in[3];
    const float* Wk   = (const float*)d_in[4];
    const float* bk   = (const float*)d_in[5];
    const float* Wv   = (const float*)d_in[6];
    const float* bv   = (const float*)d_in[7];
    const float* Wo   = (const float*)d_in[8];
    const float* bo   = (const float*)d_in[9];
    const float* ln1g = (const float*)d_in[10];
    const float* ln1b = (const float*)d_in[11];
    const float* Wm   = (const float*)d_in[12];
    const float* bmv  = (const float*)d_in[13];
    const float* Wr   = (const float*)d_in[14];
    const float* br   = (const float*)d_in[15];
    const float* ln2g = (const float*)d_in[16];
    const float* ln2b = (const float*)d_in[17];
    const float* Wp   = (const float*)d_in[18];
    const float* bp   = (const float*)d_in[19];
    float* out = (float*)d_out;

    static h16 *wh = nullptr, *xh, *xl, *qh, *ql, *kh;
    static h16 *vth, *t0h, *t0l, *ph, *pl, *ih, *il;
    static float *px, *py, *psc;
    if (!wh) {
        cudaGetSymbolAddress((void**)&wh, g_wh);
        cudaGetSymbolAddress((void**)&xh, g_xh);   cudaGetSymbolAddress((void**)&xl, g_xl);
        cudaGetSymbolAddress((void**)&qh, g_qh);   cudaGetSymbolAddress((void**)&ql, g_ql);
        cudaGetSymbolAddress((void**)&kh, g_kh);
        cudaGetSymbolAddress((void**)&vth, g_vth);
        cudaGetSymbolAddress((void**)&t0h, g_t0h); cudaGetSymbolAddress((void**)&t0l, g_t0l);
        cudaGetSymbolAddress((void**)&ph, g_ph);   cudaGetSymbolAddress((void**)&pl, g_pl);
        cudaGetSymbolAddress((void**)&ih, g_ih);   cudaGetSymbolAddress((void**)&il, g_il);
        cudaGetSymbolAddress((void**)&px, g_x);    cudaGetSymbolAddress((void**)&py, g_y);
        cudaGetSymbolAddress((void**)&psc, g_scores);
        cudaFuncSetAttribute((const void*)tgemm<128,0,0,false>, cudaFuncAttributeMaxDynamicSharedMemorySize, S128);
        cudaFuncSetAttribute((const void*)tgemm<128,0,1,true>,  cudaFuncAttributeMaxDynamicSharedMemorySize, S128);
        cudaFuncSetAttribute((const void*)tgemm<128,0,1,false>, cudaFuncAttributeMaxDynamicSharedMemorySize, S128);
        cudaFuncSetAttribute((const void*)tgemm<128,0,2,false>, cudaFuncAttributeMaxDynamicSharedMemorySize, S128);
        cudaFuncSetAttribute((const void*)tgemm<64,0,1,true>,   cudaFuncAttributeMaxDynamicSharedMemorySize, S64);
        cudaFuncSetAttribute((const void*)tgemm<128,1,1,true>,  cudaFuncAttributeMaxDynamicSharedMemorySize, S128);
        cudaFuncSetAttribute((const void*)tgemm<128,1,0,false>, cudaFuncAttributeMaxDynamicSharedMemorySize, S128);
    }

    const ll Z = 0;
    const ll DD = (ll)ND * ND;
    dim3 t32(32, 8);

    // layer-0 weights needed first; ordered so launch #6 is the Q-proj tgemm (ncu -s 5)
    {
        ll o = 0;
        wsplit_kernel<<<dim3(ND/32, ND/32), t32>>>(Wq, wh + o,        ND, ND);   // 1
        wsplit_kernel<<<dim3(ND/32, ND/32), t32>>>(Wk, wh + o + DD,   ND, ND);   // 2
        wsplit_kernel<<<dim3(ND/32, ND/32), t32>>>(Wv, wh + o + 2*DD, ND, ND);   // 3
        wsplit_kernel<<<dim3(ND/32, ND/32), t32>>>(Wo, wh + o + 3*DD, ND, ND);   // 4
        concat_kernel<<<(NBT * ND / 4 + 255) / 256, 256>>>(hs, mem);             // 5
        tgemm<128,0,1,true><<<dim3(8, 32, 1), 256, S128>>>(xh, xl, wh + o, bq, 1.f,   // 6 <- ncu
            nullptr, qh, ql, ND, ND, ND, ND, Z,Z,Z,Z,Z,Z, 1);
        wsplit_kernel<<<dim3(NI/32, ND/32), t32>>>(Wm, wh + o + 4*DD, ND, NI);
        wsplit_kernel<<<dim3(ND/32, NI/32), t32>>>(Wr, wh + o + 4*DD + (ll)ND*NI, NI, ND);
    }
    for (int l = 1; l < NL; l++) {
        ll o = (ll)l * WPL;
        wsplit_kernel<<<dim3(ND/32, ND/32), t32>>>(Wq + l*DD, wh + o,        ND, ND);
        wsplit_kernel<<<dim3(ND/32, ND/32), t32>>>(Wk + l*DD, wh + o + DD,   ND, ND);
        wsplit_kernel<<<dim3(ND/32, ND/32), t32>>>(Wv + l*DD, wh + o + 2*DD, ND, ND);
        wsplit_kernel<<<dim3(ND/32, ND/32), t32>>>(Wo + l*DD, wh + o + 3*DD, ND, ND);
        wsplit_kernel<<<dim3(NI/32, ND/32), t32>>>(Wm + (ll)l*ND*NI, wh + o + 4*DD, ND, NI);
        wsplit_kernel<<<dim3(ND/32, NI/32), t32>>>(Wr + (ll)l*NI*ND, wh + o + 4*DD + (ll)ND*NI, NI, ND);
    }
    wsplit_kernel<<<dim3(NOUT/32, ND/32), t32>>>(Wp, wh + (ll)NL*WPL, ND, NOUT);

    for (int l = 0; l < NL; l++) {
        ll o = (ll)l * WPL;
        const h16 *wqh = wh + o;
        const h16 *wkh = wh + o + DD;
        const h16 *wvh = wh + o + 2*DD;
        const h16 *woh = wh + o + 3*DD;
        const h16 *wmh = wh + o + 4*DD;
        const h16 *wrh = wh + o + 4*DD + (ll)ND*NI;

        if (l > 0)
            tgemm<128,0,1,true><<<dim3(8, 32, 1), 256, S128>>>(xh, xl, wqh, bq + l*ND, 1.f,
                nullptr, qh, ql, ND, ND, ND, ND, Z,Z,Z,Z,Z,Z, 1);
        tgemm<128,0,1,false><<<dim3(8, 32, 1), 256, S128>>>(xh, xl, wkh, bk + l*ND, 1.f,
            nullptr, kh, nullptr, ND, ND, ND, ND, Z,Z,Z,Z,Z,Z, 1);
        tgemm<128,0,2,false><<<dim3(8, 32, 1), 256, S128>>>(xh, xl, wvh, bv + l*ND, 1.f,
            nullptr, vth, nullptr, ND, ND, ND, NBT, Z,Z,Z,Z,Z,Z, 1);

        tgemm<128,0,0,false><<<dim3(8, 8, NB*NH), 256, S128>>>(qh, ql, kh, nullptr, 0.125f,
            psc, nullptr, nullptr, NDH, ND, ND, NT,
            (ll)NT*ND, (ll)NDH, (ll)NT*ND, (ll)NDH, (ll)NH*NT*NT, (ll)NT*NT, NH);

        softmax_kernel<<<NB*NH*NT, 256>>>();

        tgemm<64,0,1,true><<<dim3(1, 8, NB*NH), 256, S64>>>(ph, pl, vth, nullptr, 1.f,
            nullptr, t0h, t0l, NT, NT, NBT, ND,
            (ll)NH*NT*NT, (ll)NT*NT, (ll)NT, (ll)NDH*NBT, (ll)NT*ND, (ll)NDH, NH);

        tgemm<128,0,0,false><<<dim3(8, 32, 1), 256, S128>>>(t0h, t0l, woh, bo + l*ND, 1.f,
            py, nullptr, nullptr, ND, ND, ND, ND, Z,Z,Z,Z,Z,Z, 1);
        add_ln_kernel<<<NBT, 256>>>(py, ln1g + l*ND, ln1b + l*ND);

        tgemm<128,1,1,true><<<dim3(32, 32, 1), 256, S128>>>(xh, xl, wmh, bmv + l*NI, 1.f,
            nullptr, ih, il, ND, ND, ND, NI, Z,Z,Z,Z,Z,Z, 1);
        tgemm<128,0,0,false><<<dim3(8, 32, 1), 256, S128>>>(ih, il, wrh, br + l*ND, 1.f,
            py, nullptr, nullptr, NI, NI, NI, ND, Z,Z,Z,Z,Z,Z, 1);
        add_ln_kernel<<<NBT, 256>>>(py, ln2g + l*ND, ln2b + l*ND);
    }

    tgemm<128,1,0,false><<<dim3(32, 7, NB), 256, S128>>>(xh + NM*ND, xl + NM*ND,
        wh + (ll)NL*WPL, bp, 1.f,
        out, nullptr, nullptr, ND, ND, ND, NOUT,
        (ll)NT*ND, Z, Z, Z, (ll)NS*NOUT, Z, 1);

    readout_kernel<<<(NB * NM * ND + 255) / 256, 256>>>(out);
}

// round 7
// speedup vs baseline: 4.1285x; 1.1298x over previous
#include <cuda_runtime.h>
#include <cuda_fp16.h>
#include <math.h>
#include <stdint.h>

#define NB   4
#define NS   896
#define ND   1024
#define NH   16
#define NDH  64
#define NI   4096
#define NOUT 4096
#define NL   2
#define NM   128
#define NT   1024
#define NBT  4096

typedef __half h16;
typedef long long ll;

__device__ float g_x[NBT * ND];
__device__ float g_y[NBT * ND];
__device__ h16  g_xh[NBT * ND],  g_xl[NBT * ND];
__device__ h16  g_qh[NBT * ND],  g_ql[NBT * ND];
__device__ h16  g_kh[NBT * ND];
__device__ h16  g_vth[NBT * ND];
__device__ h16  g_t0h[NBT * ND], g_t0l[NBT * ND];
__device__ h16  g_ih[(size_t)NBT * NI], g_il[(size_t)NBT * NI];
#define WPL (4 * ND * ND + ND * NI + NI * ND)
#define WELEMS (NL * WPL + ND * NOUT)
__device__ h16  g_wh[WELEMS];

__device__ __forceinline__ uint32_t smem_u32(const void* p) {
    uint32_t a;
    asm("{ .reg .u64 t; cvta.to.shared.u64 t, %1; cvt.u32.u64 %0, t; }" : "=r"(a) : "l"(p));
    return a;
}
__device__ __forceinline__ float gelu_f(float x) {
    return 0.5f * x * (1.0f + erff(x * 0.7071067811865476f));
}
__device__ __forceinline__ void split2(float v, h16& h, h16& l) {
    h = __float2half_rn(v);
    l = __float2half_rn(v - __half2float(h));
}
__device__ __forceinline__ void ldsm4(uint32_t& r0, uint32_t& r1, uint32_t& r2, uint32_t& r3, uint32_t a) {
    asm volatile("ldmatrix.sync.aligned.m8n8.x4.shared.b16 {%0,%1,%2,%3}, [%4];"
                 : "=r"(r0), "=r"(r1), "=r"(r2), "=r"(r3) : "r"(a));
}
__device__ __forceinline__ void mma16816(float* c, const uint32_t* a, const uint32_t* b) {
    asm volatile("mma.sync.aligned.m16n8k16.row.col.f32.f16.f16.f32 "
                 "{%0,%1,%2,%3},{%4,%5,%6,%7},{%8,%9},{%0,%1,%2,%3};"
                 : "+f"(c[0]), "+f"(c[1]), "+f"(c[2]), "+f"(c[3])
                 : "r"(a[0]), "r"(a[1]), "r"(a[2]), "r"(a[3]), "r"(b[0]), "r"(b[1]));
}
__device__ __forceinline__ void cpasync16(uint32_t dst, const void* src) {
    asm volatile("cp.async.cg.shared.global [%0], [%1], 16;" :: "r"(dst), "l"(src));
}
__device__ __forceinline__ void cpcommit() { asm volatile("cp.async.commit_group;" ::: "memory"); }
template<int N> __device__ __forceinline__ void cpwait() {
    asm volatile("cp.async.wait_group %0;" :: "n"(N) : "memory");
}
__device__ __forceinline__ uint32_t swoff(int r, int c16) {
    return (uint32_t)(r * 128 + ((c16 ^ (r & 7)) * 16));
}
__device__ __forceinline__ uint32_t packh(float a, float b) {
    __half2 p = __halves2half2(__float2half_rn(a), __float2half_rn(b));
    return *reinterpret_cast<uint32_t*>(&p);
}

// ---------------- split-fp16 warp-MMA GEMM (2-term: AhBh + AlBh) ----------------
template<int BN, int ACT, int OUTM, bool WLO>
__global__ void __launch_bounds__(256, 2) tgemm(
    const h16* __restrict__ Ah, const h16* __restrict__ Al,
    const h16* __restrict__ Bh,
    const float* __restrict__ bias, float alpha,
    float* __restrict__ Cf, h16* __restrict__ Ch, h16* __restrict__ Cl,
    int K, int lda, int ldb, int ldc,
    ll oA, ll iA, ll oB, ll iB, ll oC, ll iC, int h)
{
    constexpr int ABYTES = 128 * 128;
    constexpr int BBYTES = BN * 128;
    constexpr int STAGE  = 2 * ABYTES + BBYTES;
    constexpr int WN     = BN / 2;
    constexpr int NT8    = WN / 8;

    extern __shared__ __align__(128) char smem[];
    const uint32_t sb = smem_u32(smem);
    const int tid = threadIdx.x, lane = tid & 31, wid = tid >> 5;
    const int wm = wid >> 1, wn = wid & 1;

    const int z = blockIdx.z;
    const ll aoff = (ll)(z / h) * oA + (ll)(z % h) * iA;
    const ll boff = (ll)(z / h) * oB + (ll)(z % h) * iB;
    const ll coff = (ll)(z / h) * oC + (ll)(z % h) * iC;
    const int bm = blockIdx.y * 128;
    const int bn = blockIdx.x * BN;
    const h16* a0h = Ah + aoff + (ll)bm * lda;
    const h16* a0l = Al + aoff + (ll)bm * lda;
    const h16* b0h = Bh + boff + (ll)bn * ldb;

    float acc[2][NT8][4];
#pragma unroll
    for (int i = 0; i < 2; i++)
#pragma unroll
        for (int j = 0; j < NT8; j++)
#pragma unroll
            for (int t = 0; t < 4; t++) acc[i][j][t] = 0.0f;

    const int nch = K >> 6;
    const int aRow = (lane & 7) | (((lane >> 3) & 1) << 3);
    const int aC   = lane >> 4;
    const int bRow = (lane & 7) | (((lane >> 4) & 1) << 3);
    const int bC   = (lane >> 3) & 1;

    auto issue = [&](int c, int s) {
        const int k0 = c * 64;
        const uint32_t base = sb + s * STAGE;
        constexpr int TOT = (2 * 128 + BN) * 8;
#pragma unroll 4
        for (int u = tid; u < TOT; u += 256) {
            const int chunk = u & 7, row = u >> 3;
            const h16* src; uint32_t dbase; int r, ld;
            if (row < 128)       { src = a0h; r = row;       dbase = base;              ld = lda; }
            else if (row < 256)  { src = a0l; r = row - 128; dbase = base + ABYTES;     ld = lda; }
            else                 { src = b0h; r = row - 256; dbase = base + 2 * ABYTES; ld = ldb; }
            cpasync16(dbase + swoff(r, chunk), src + (ll)r * ld + k0 + chunk * 8);
        }
    };

    issue(0, 0);
    cpcommit();

    for (int c = 0; c < nch; c++) {
        if (c + 1 < nch) { issue(c + 1, (c + 1) & 1); cpcommit(); cpwait<1>(); }
        else             { cpwait<0>(); }
        __syncthreads();

        const uint32_t tAh = sb + (c & 1) * STAGE;
        const uint32_t tAl = tAh + ABYTES;
        const uint32_t tBh = tAh + 2 * ABYTES;

#pragma unroll
        for (int ks = 0; ks < 4; ks++) {
            uint32_t ah[2][4], al[2][4], bh[NT8][2];
#pragma unroll
            for (int mt = 0; mt < 2; mt++) {
                const int r = wm * 32 + mt * 16 + aRow;
                const int c16 = ks * 2 + aC;
                ldsm4(ah[mt][0], ah[mt][1], ah[mt][2], ah[mt][3], tAh + swoff(r, c16));
                ldsm4(al[mt][0], al[mt][1], al[mt][2], al[mt][3], tAl + swoff(r, c16));
            }
#pragma unroll
            for (int nt2 = 0; nt2 < NT8 / 2; nt2++) {
                const int r = wn * WN + nt2 * 16 + bRow;
                const int c16 = ks * 2 + bC;
                ldsm4(bh[2*nt2][0], bh[2*nt2][1], bh[2*nt2+1][0], bh[2*nt2+1][1], tBh + swoff(r, c16));
            }
#pragma unroll
            for (int mt = 0; mt < 2; mt++)
#pragma unroll
                for (int nt = 0; nt < NT8; nt++) {
                    mma16816(acc[mt][nt], ah[mt], bh[nt]);
                    mma16816(acc[mt][nt], al[mt], bh[nt]);
                }
        }
        __syncthreads();
    }

    const int gid = lane >> 2, tig2 = (lane & 3) * 2;

    if (OUTM == 2) {
        constexpr int TSTRIDE = 272;
#pragma unroll
        for (int mt = 0; mt < 2; mt++)
#pragma unroll
            for (int nt = 0; nt < NT8; nt++) {
                const int nl = wn * WN + nt * 8 + tig2;
#pragma unroll
                for (int hf = 0; hf < 2; hf++) {
                    const int ml = wm * 32 + mt * 16 + gid + hf * 8;
                    h16 h0 = __float2half_rn(acc[mt][nt][hf * 2]     * alpha);
                    h16 h1 = __float2half_rn(acc[mt][nt][hf * 2 + 1] * alpha);
                    *reinterpret_cast<h16*>(smem + nl * TSTRIDE + ml * 2) = h0;
                    *reinterpret_cast<h16*>(smem + (nl + 1) * TSTRIDE + ml * 2) = h1;
                }
            }
        __syncthreads();
        for (int u = tid; u < BN * 16; u += 256) {
            const int nl = u >> 4, c16 = (u & 15) * 8;
            uint4 v = *reinterpret_cast<const uint4*>(smem + nl * TSTRIDE + c16 * 2);
            if (bias) {
                h16* hv = reinterpret_cast<h16*>(&v);
                const float bb = bias[bn + nl];
#pragma unroll
                for (int t = 0; t < 8; t++) hv[t] = __float2half_rn(__half2float(hv[t]) + bb);
            }
            *reinterpret_cast<uint4*>(Ch + coff + (ll)(bn + nl) * ldc + bm + c16) = v;
        }
        return;
    }

#pragma unroll
    for (int mt = 0; mt < 2; mt++) {
#pragma unroll
        for (int nt = 0; nt < NT8; nt++) {
            const int n = bn + wn * WN + nt * 8 + tig2;
            float bv0 = 0.f, bv1 = 0.f;
            if (bias) { bv0 = bias[n]; bv1 = bias[n + 1]; }
#pragma unroll
            for (int hf = 0; hf < 2; hf++) {
                const int m = bm + wm * 32 + mt * 16 + gid + hf * 8;
                float v0 = acc[mt][nt][hf * 2]     * alpha + bv0;
                float v1 = acc[mt][nt][hf * 2 + 1] * alpha + bv1;
                if (ACT) { v0 = gelu_f(v0); v1 = gelu_f(v1); }
                if (OUTM == 0) {
                    *reinterpret_cast<float2*>(Cf + coff + (ll)m * ldc + n) = make_float2(v0, v1);
                } else {
                    h16 h0, l0, h1, l1;
                    split2(v0, h0, l0); split2(v1, h1, l1);
                    *reinterpret_cast<__half2*>(Ch + coff + (ll)m * ldc + n) = __halves2half2(h0, h1);
                    if (WLO)
                        *reinterpret_cast<__half2*>(Cl + coff + (ll)m * ldc + n) = __halves2half2(l0, l1);
                }
            }
        }
    }
}

// ---------------- fused flash attention ----------------
// grid (8, 64): x = q block, y = b*NH+h. 8 warps: wm 0..3 (32 rows), wn 0..1 (64 S cols).
#define FSMEM 100864
__global__ void __launch_bounds__(256, 1) flash_kernel(
    const h16* __restrict__ Qh, const h16* __restrict__ Ql,
    const h16* __restrict__ Kh, const h16* __restrict__ Vt,
    h16* __restrict__ Oh, h16* __restrict__ Ol)
{
    extern __shared__ __align__(128) char smem[];
    const uint32_t sb = smem_u32(smem);
    const int tid = threadIdx.x, lane = tid & 31, wid = tid >> 5;
    const int wm = wid >> 1, wn = wid & 1;
    const int qb = blockIdx.x;
    const int z = blockIdx.y, b = z >> 4, hh = z & 15;

    const h16* q0h = Qh + (ll)(b * NT + qb * 128) * ND + hh * 64;
    const h16* q0l = Ql + (ll)(b * NT + qb * 128) * ND + hh * 64;
    const h16* k0  = Kh + (ll)(b * NT) * ND + hh * 64;
    const h16* v0  = Vt + (ll)(hh * 64) * NBT + b * NT;

    for (int u = tid; u < 2048; u += 256) {
        int which = u >> 10, r = (u >> 3) & 127, c = u & 7;
        const h16* src = which ? q0l : q0h;
        cpasync16(sb + which * 16384 + swoff(r, c), src + (ll)r * ND + c * 8);
    }
    auto issueKV = [&](int t) {
        const int s = t & 1;
        const uint32_t kb = sb + 32768 + s * 16384;
        const uint32_t vb = sb + 65536 + s * 16384;
        for (int u = tid; u < 1024; u += 256) {
            int r = u >> 3, c = u & 7;
            cpasync16(kb + swoff(r, c), k0 + (ll)(t * 128 + r) * ND + c * 8);
        }
        for (int u = tid; u < 1024; u += 256) {
            int half = u >> 9, r = (u >> 3) & 63, c = u & 7;
            cpasync16(vb + half * 8192 + swoff(r, c),
                      v0 + (ll)r * NBT + t * 128 + half * 64 + c * 8);
        }
    };
    issueKV(0); cpcommit();

    const int aRow = (lane & 7) | (((lane >> 3) & 1) << 3);
    const int aC   = lane >> 4;
    const int bRow = (lane & 7) | (((lane >> 4) & 1) << 3);
    const int bC   = (lane >> 3) & 1;
    const int gid  = lane >> 2, tig2 = (lane & 3) * 2;

    float oacc[2][8][4];
#pragma unroll
    for (int i = 0; i < 2; i++)
#pragma unroll
        for (int j = 0; j < 8; j++)
#pragma unroll
            for (int t = 0; t < 4; t++) oacc[i][j][t] = 0.0f;
    float mrow[2][2] = {{-1e30f, -1e30f}, {-1e30f, -1e30f}};
    float lsum[2][2] = {{0.f, 0.f}, {0.f, 0.f}};

    float* redmax = (float*)(smem + 98304);
    float* redsum = (float*)(smem + 99328);

    for (int t = 0; t < 8; t++) {
        if (t < 7) { issueKV(t + 1); cpcommit(); cpwait<1>(); }
        else       { cpwait<0>(); }
        __syncthreads();
        const uint32_t kb = sb + 32768 + (t & 1) * 16384;
        const uint32_t vb = sb + 65536 + (t & 1) * 16384 + wn * 8192;

        float sacc[2][8][4];
#pragma unroll
        for (int i = 0; i < 2; i++)
#pragma unroll
            for (int j = 0; j < 8; j++)
#pragma unroll
                for (int u = 0; u < 4; u++) sacc[i][j][u] = 0.0f;

#pragma unroll
        for (int kc = 0; kc < 4; kc++) {
            uint32_t ah[2][4], al[2][4], bh[8][2];
#pragma unroll
            for (int mt = 0; mt < 2; mt++) {
                const int r = wm * 32 + mt * 16 + aRow;
                const int c16 = kc * 2 + aC;
                ldsm4(ah[mt][0], ah[mt][1], ah[mt][2], ah[mt][3], sb + swoff(r, c16));
                ldsm4(al[mt][0], al[mt][1], al[mt][2], al[mt][3], sb + 16384 + swoff(r, c16));
            }
#pragma unroll
            for (int nt2 = 0; nt2 < 4; nt2++) {
                const int r = wn * 64 + nt2 * 16 + bRow;
                const int c16 = kc * 2 + bC;
                ldsm4(bh[2*nt2][0], bh[2*nt2][1], bh[2*nt2+1][0], bh[2*nt2+1][1], kb + swoff(r, c16));
            }
#pragma unroll
            for (int mt = 0; mt < 2; mt++)
#pragma unroll
                for (int nt = 0; nt < 8; nt++) {
                    mma16816(sacc[mt][nt], ah[mt], bh[nt]);
                    mma16816(sacc[mt][nt], al[mt], bh[nt]);
                }
        }
#pragma unroll
        for (int i = 0; i < 2; i++)
#pragma unroll
            for (int j = 0; j < 8; j++)
#pragma unroll
                for (int u = 0; u < 4; u++) sacc[i][j][u] *= 0.125f;

        // row max (warp half, then cross-warp)
        float pmax[2][2];
#pragma unroll
        for (int mt = 0; mt < 2; mt++)
#pragma unroll
            for (int hf = 0; hf < 2; hf++) {
                float v = -1e30f;
#pragma unroll
                for (int nt = 0; nt < 8; nt++)
                    v = fmaxf(v, fmaxf(sacc[mt][nt][hf*2], sacc[mt][nt][hf*2+1]));
                v = fmaxf(v, __shfl_xor_sync(0xffffffffu, v, 1));
                v = fmaxf(v, __shfl_xor_sync(0xffffffffu, v, 2));
                pmax[mt][hf] = v;
            }
        if ((lane & 3) == 0) {
#pragma unroll
            for (int mt = 0; mt < 2; mt++)
#pragma unroll
                for (int hf = 0; hf < 2; hf++)
                    redmax[wn * 128 + wm*32 + mt*16 + hf*8 + gid] = pmax[mt][hf];
        }
        __syncthreads();
        float scl[2][2];
#pragma unroll
        for (int mt = 0; mt < 2; mt++)
#pragma unroll
            for (int hf = 0; hf < 2; hf++) {
                const int r = wm*32 + mt*16 + hf*8 + gid;
                float tm = fmaxf(pmax[mt][hf], redmax[(wn^1) * 128 + r]);
                float mi = fmaxf(mrow[mt][hf], tm);
                scl[mt][hf] = __expf(mrow[mt][hf] - mi);
                mrow[mt][hf] = mi;
            }
        // p = exp(s - m), partial row sums
        float psum[2][2] = {{0.f,0.f},{0.f,0.f}};
#pragma unroll
        for (int mt = 0; mt < 2; mt++)
#pragma unroll
            for (int nt = 0; nt < 8; nt++)
#pragma unroll
                for (int j = 0; j < 4; j++) {
                    const int hf = j >> 1;
                    float p = __expf(sacc[mt][nt][j] - mrow[mt][hf]);
                    sacc[mt][nt][j] = p;
                    psum[mt][hf] += p;
                }
#pragma unroll
        for (int mt = 0; mt < 2; mt++)
#pragma unroll
            for (int hf = 0; hf < 2; hf++) {
                psum[mt][hf] += __shfl_xor_sync(0xffffffffu, psum[mt][hf], 1);
                psum[mt][hf] += __shfl_xor_sync(0xffffffffu, psum[mt][hf], 2);
            }
        __syncthreads();
        if ((lane & 3) == 0) {
#pragma unroll
            for (int mt = 0; mt < 2; mt++)
#pragma unroll
                for (int hf = 0; hf < 2; hf++)
                    redsum[wn * 128 + wm*32 + mt*16 + hf*8 + gid] = psum[mt][hf];
        }
        __syncthreads();
#pragma unroll
        for (int mt = 0; mt < 2; mt++)
#pragma unroll
            for (int hf = 0; hf < 2; hf++) {
                const int r = wm*32 + mt*16 + hf*8 + gid;
                float tot = psum[mt][hf] + redsum[(wn^1) * 128 + r];
                lsum[mt][hf] = lsum[mt][hf] * scl[mt][hf] + tot;
            }
        // rescale O
#pragma unroll
        for (int mt = 0; mt < 2; mt++)
#pragma unroll
            for (int dt = 0; dt < 8; dt++)
#pragma unroll
                for (int j = 0; j < 4; j++) oacc[mt][dt][j] *= scl[mt][j >> 1];

        // P @ V (hi + lo terms); A-frags from sacc (C-frag == A-frag half layout)
#pragma unroll
        for (int kk = 0; kk < 4; kk++) {
            uint32_t bfr[8][2];
#pragma unroll
            for (int dt2 = 0; dt2 < 4; dt2++) {
                const int r = dt2 * 16 + bRow;
                const int c16 = kk * 2 + bC;
                ldsm4(bfr[2*dt2][0], bfr[2*dt2][1], bfr[2*dt2+1][0], bfr[2*dt2+1][1], vb + swoff(r, c16));
            }
            uint32_t aH[2][4], aL[2][4];
#pragma unroll
            for (int mt = 0; mt < 2; mt++) {
#pragma unroll
                for (int q = 0; q < 4; q++) {
                    const int nt = 2 * kk + (q >> 1);
                    const int j0 = (q & 1) * 2;
                    float v0 = sacc[mt][nt][j0], v1 = sacc[mt][nt][j0 + 1];
                    h16 h0, l0, h1, l1;
                    split2(v0, h0, l0); split2(v1, h1, l1);
                    __half2 H = __halves2half2(h0, h1), L = __halves2half2(l0, l1);
                    aH[mt][q] = *reinterpret_cast<uint32_t*>(&H);
                    aL[mt][q] = *reinterpret_cast<uint32_t*>(&L);
                }
            }
#pragma unroll
            for (int mt = 0; mt < 2; mt++)
#pragma unroll
                for (int dt = 0; dt < 8; dt++) {
                    mma16816(oacc[mt][dt], aH[mt], bfr[dt]);
                    mma16816(oacc[mt][dt], aL[mt], bfr[dt]);
                }
        }
        __syncthreads();
    }

    // epilogue: combine wn halves, divide by l, write hi/lo
    float* lb = (float*)(smem + 100352);
    if (wn == 0 && (lane & 3) == 0) {
#pragma unroll
        for (int mt = 0; mt < 2; mt++)
#pragma unroll
            for (int hf = 0; hf < 2; hf++)
                lb[wm*32 + mt*16 + hf*8 + gid] = lsum[mt][hf];
    }
    float* obuf = (float*)smem;
    const int OST = 68;
    if (wn == 0) {
#pragma unroll
        for (int mt = 0; mt < 2; mt++)
#pragma unroll
            for (int dt = 0; dt < 8; dt++)
#pragma unroll
                for (int j = 0; j < 4; j++)
                    obuf[(wm*32 + mt*16 + (j>>1)*8 + gid) * OST + dt*8 + tig2 + (j&1)] = oacc[mt][dt][j];
    }
    __syncthreads();
    if (wn == 1) {
#pragma unroll
        for (int mt = 0; mt < 2; mt++)
#pragma unroll
            for (int dt = 0; dt < 8; dt++)
#pragma unroll
                for (int j = 0; j < 4; j++)
                    obuf[(wm*32 + mt*16 + (j>>1)*8 + gid) * OST + dt*8 + tig2 + (j&1)] += oacc[mt][dt][j];
    }
    __syncthreads();
    h16* oh = Oh + (ll)(b * NT + qb * 128) * ND + hh * 64;
    h16* ol = Ol + (ll)(b * NT + qb * 128) * ND + hh * 64;
    for (int u = tid; u < 8192; u += 256) {
        const int r = u >> 6, d = u & 63;
        float v = obuf[r * OST + d] / lb[r];
        h16 hv, lv; split2(v, hv, lv);
        oh[(ll)r * ND + d] = hv;
        ol[(ll)r * ND + d] = lv;
    }
}

// W[K,N] -> Th[N,K] (hi only)
__global__ void __launch_bounds__(256) wsplit_kernel(const float* __restrict__ W,
                                                     h16* __restrict__ Th, int K, int N) {
    __shared__ float t[32][33];
    const int n0 = blockIdx.x * 32, k0 = blockIdx.y * 32;
    const int tx = threadIdx.x, ty = threadIdx.y;
#pragma unroll
    for (int i = 0; i < 4; i++)
        t[ty + i * 8][tx] = W[(ll)(k0 + ty + i * 8) * N + n0 + tx];
    __syncthreads();
#pragma unroll
    for (int i = 0; i < 4; i++) {
        int n = ty + i * 8;
        Th[(ll)(n0 + n) * K + k0 + tx] = __float2half_rn(t[tx][n]);
    }
}

__global__ void concat_kernel(const float* __restrict__ hs, const float* __restrict__ mem) {
    int i4 = blockIdx.x * blockDim.x + threadIdx.x;
    if (i4 >= NBT * ND / 4) return;
    int idx = i4 * 4;
    int d = idx % ND;
    int t = (idx / ND) % NT;
    int b = idx / (ND * NT);
    float4 v = (t < NM) ? *reinterpret_cast<const float4*>(mem + t * ND + d)
                        : *reinterpret_cast<const float4*>(hs + ((size_t)(b * NS + t - NM)) * ND + d);
    *reinterpret_cast<float4*>(g_x + idx) = v;
    h16 H[4], L[4];
    split2(v.x, H[0], L[0]); split2(v.y, H[1], L[1]);
    split2(v.z, H[2], L[2]); split2(v.w, H[3], L[3]);
    *reinterpret_cast<__half2*>(g_xh + idx)     = __halves2half2(H[0], H[1]);
    *reinterpret_cast<__half2*>(g_xh + idx + 2) = __halves2half2(H[2], H[3]);
    *reinterpret_cast<__half2*>(g_xl + idx)     = __halves2half2(L[0], L[1]);
    *reinterpret_cast<__half2*>(g_xl + idx + 2) = __halves2half2(L[2], L[3]);
}

__global__ void __launch_bounds__(256) add_ln_kernel(const float* __restrict__ y,
                                                     const float* __restrict__ gam,
                                                     const float* __restrict__ bet) {
    __shared__ float red[8];
    __shared__ float s0, s1;
    const int tid = threadIdx.x;
    const size_t base = (size_t)blockIdx.x * ND;
    const int c = tid * 4;
    float4 a = *reinterpret_cast<const float4*>(y + base + c);
    float4 xo = *reinterpret_cast<const float4*>(g_x + base + c);
    float v0 = a.x + xo.x, v1 = a.y + xo.y, v2 = a.z + xo.z, v3 = a.w + xo.w;
    float s = v0 + v1 + v2 + v3;
    for (int o = 16; o > 0; o >>= 1) s += __shfl_xor_sync(0xffffffffu, s, o);
    if ((tid & 31) == 0) red[tid >> 5] = s;
    __syncthreads();
    if (tid == 0) { float t = 0; for (int i = 0; i < 8; i++) t += red[i]; s0 = t * (1.0f / ND); }
    __syncthreads();
    const float mean = s0;
    float d0 = v0 - mean, d1 = v1 - mean, d2 = v2 - mean, d3 = v3 - mean;
    float vs = d0*d0 + d1*d1 + d2*d2 + d3*d3;
    for (int o = 16; o > 0; o >>= 1) vs += __shfl_xor_sync(0xffffffffu, vs, o);
    if ((tid & 31) == 0) red[tid >> 5] = vs;
    __syncthreads();
    if (tid == 0) { float t = 0; for (int i = 0; i < 8; i++) t += red[i]; s1 = rsqrtf(t * (1.0f / ND) + 1e-12f); }
    __syncthreads();
    const float inv = s1;
    float4 gv = *reinterpret_cast<const float4*>(gam + c);
    float4 bv = *reinterpret_cast<const float4*>(bet + c);
    float r0 = d0*inv*gv.x + bv.x, r1 = d1*inv*gv.y + bv.y;
    float r2 = d2*inv*gv.z + bv.z, r3 = d3*inv*gv.w + bv.w;
    *reinterpret_cast<float4*>(g_x + base + c) = make_float4(r0, r1, r2, r3);
    h16 H[4], L[4];
    split2(r0, H[0], L[0]); split2(r1, H[1], L[1]);
    split2(r2, H[2], L[2]); split2(r3, H[3], L[3]);
    *reinterpret_cast<__half2*>(g_xh + base + c)     = __halves2half2(H[0], H[1]);
    *reinterpret_cast<__half2*>(g_xh + base + c + 2) = __halves2half2(H[2], H[3]);
    *reinterpret_cast<__half2*>(g_xl + base + c)     = __halves2half2(L[0], L[1]);
    *reinterpret_cast<__half2*>(g_xl + base + c + 2) = __halves2half2(L[2], L[3]);
}

__global__ void readout_kernel(float* __restrict__ out) {
    int idx = blockIdx.x * blockDim.x + threadIdx.x;
    if (idx >= NB * NM * ND) return;
    int d = idx % ND;
    int t = (idx / ND) % NM;
    int b = idx / (ND * NM);
    out[(size_t)NB * NS * NOUT + idx] = g_x[((size_t)b * NT + t) * ND + d];
}

#define S128 (2 * (2 * 128 * 128 + 128 * 128))   // 98304
#define S64  (2 * (2 * 128 * 128 + 64 * 128))    // 81920

extern "C" void kernel_launch(void* const* d_in, const int* in_sizes, int n_in,
                              void* d_out, int out_size) {
    const float* hs   = (const float*)d_in[0];
    const float* mem  = (const float*)d_in[1];
    const float* Wq   = (const float*)d_in[2];
    const float* bq   = (const float*)d_in[3];
    const float* Wk   = (const float*)d_in[4];
    const float* bk   = (const float*)d_in[5];
    const float* Wv   = (const float*)d_in[6];
    const float* bv   = (const float*)d_in[7];
    const float* Wo   = (const float*)d_in[8];
    const float* bo   = (const float*)d_in[9];
    const float* ln1g = (const float*)d_in[10];
    const float* ln1b = (const float*)d_in[11];
    const float* Wm   = (const float*)d_in[12];
    const float* bmv  = (const float*)d_in[13];
    const float* Wr   = (const float*)d_in[14];
    const float* br   = (const float*)d_in[15];
    const float* ln2g = (const float*)d_in[16];
    const float* ln2b = (const float*)d_in[17];
    const float* Wp   = (const float*)d_in[18];
    const float* bp   = (const float*)d_in[19];
    float* out = (float*)d_out;

    static h16 *wh = nullptr, *xh, *xl, *qh, *ql, *kh;
    static h16 *vth, *t0h, *t0l, *ih, *il;
    static float *px, *py;
    if (!wh) {
        cudaGetSymbolAddress((void**)&wh, g_wh);
        cudaGetSymbolAddress((void**)&xh, g_xh);   cudaGetSymbolAddress((void**)&xl, g_xl);
        cudaGetSymbolAddress((void**)&qh, g_qh);   cudaGetSymbolAddress((void**)&ql, g_ql);
        cudaGetSymbolAddress((void**)&kh, g_kh);
        cudaGetSymbolAddress((void**)&vth, g_vth);
        cudaGetSymbolAddress((void**)&t0h, g_t0h); cudaGetSymbolAddress((void**)&t0l, g_t0l);
        cudaGetSymbolAddress((void**)&ih, g_ih);   cudaGetSymbolAddress((void**)&il, g_il);
        cudaGetSymbolAddress((void**)&px, g_x);    cudaGetSymbolAddress((void**)&py, g_y);
        cudaFuncSetAttribute((const void*)tgemm<128,0,0,false>, cudaFuncAttributeMaxDynamicSharedMemorySize, S128);
        cudaFuncSetAttribute((const void*)tgemm<128,0,1,true>,  cudaFuncAttributeMaxDynamicSharedMemorySize, S128);
        cudaFuncSetAttribute((const void*)tgemm<128,0,1,false>, cudaFuncAttributeMaxDynamicSharedMemorySize, S128);
        cudaFuncSetAttribute((const void*)tgemm<128,0,2,false>, cudaFuncAttributeMaxDynamicSharedMemorySize, S128);
        cudaFuncSetAttribute((const void*)tgemm<128,1,1,true>,  cudaFuncAttributeMaxDynamicSharedMemorySize, S128);
        cudaFuncSetAttribute((const void*)tgemm<128,1,0,false>, cudaFuncAttributeMaxDynamicSharedMemorySize, S128);
        cudaFuncSetAttribute((const void*)flash_kernel, cudaFuncAttributeMaxDynamicSharedMemorySize, FSMEM);
    }

    const ll Z = 0;
    const ll DD = (ll)ND * ND;
    dim3 t32(32, 8);

    for (int l = 0; l < NL; l++) {
        ll o = (ll)l * WPL;
        wsplit_kernel<<<dim3(ND/32, ND/32), t32>>>(Wq + l*DD, wh + o,        ND, ND);
        wsplit_kernel<<<dim3(ND/32, ND/32), t32>>>(Wk + l*DD, wh + o + DD,   ND, ND);
        wsplit_kernel<<<dim3(ND/32, ND/32), t32>>>(Wv + l*DD, wh + o + 2*DD, ND, ND);
        wsplit_kernel<<<dim3(ND/32, ND/32), t32>>>(Wo + l*DD, wh + o + 3*DD, ND, ND);
        wsplit_kernel<<<dim3(NI/32, ND/32), t32>>>(Wm + (ll)l*ND*NI, wh + o + 4*DD, ND, NI);
        wsplit_kernel<<<dim3(ND/32, NI/32), t32>>>(Wr + (ll)l*NI*ND, wh + o + 4*DD + (ll)ND*NI, NI, ND);
    }
    wsplit_kernel<<<dim3(NOUT/32, ND/32), t32>>>(Wp, wh + (ll)NL*WPL, ND, NOUT);

    concat_kernel<<<(NBT * ND / 4 + 255) / 256, 256>>>(hs, mem);

    for (int l = 0; l < NL; l++) {
        ll o = (ll)l * WPL;
        const h16 *wqh = wh + o;
        const h16 *wkh = wh + o + DD;
        const h16 *wvh = wh + o + 2*DD;
        const h16 *woh = wh + o + 3*DD;
        const h16 *wmh = wh + o + 4*DD;
        const h16 *wrh = wh + o + 4*DD + (ll)ND*NI;

        tgemm<128,0,1,true><<<dim3(8, 32, 1), 256, S128>>>(xh, xl, wqh, bq + l*ND, 1.f,
            nullptr, qh, ql, ND, ND, ND, ND, Z,Z,Z,Z,Z,Z, 1);
        tgemm<128,0,1,false><<<dim3(8, 32, 1), 256, S128>>>(xh, xl, wkh, bk + l*ND, 1.f,
            nullptr, kh, nullptr, ND, ND, ND, ND, Z,Z,Z,Z,Z,Z, 1);
        tgemm<128,0,2,false><<<dim3(8, 32, 1), 256, S128>>>(xh, xl, wvh, bv + l*ND, 1.f,
            nullptr, vth, nullptr, ND, ND, ND, NBT, Z,Z,Z,Z,Z,Z, 1);

        flash_kernel<<<dim3(8, 64), 256, FSMEM>>>(qh, ql, kh, vth, t0h, t0l);

        tgemm<128,0,0,false><<<dim3(8, 32, 1), 256, S128>>>(t0h, t0l, woh, bo + l*ND, 1.f,
            py, nullptr, nullptr, ND, ND, ND, ND, Z,Z,Z,Z,Z,Z, 1);
        add_ln_kernel<<<NBT, 256>>>(py, ln1g + l*ND, ln1b + l*ND);

        tgemm<128,1,1,true><<<dim3(32, 32, 1), 256, S128>>>(xh, xl, wmh, bmv + l*NI, 1.f,
            nullptr, ih, il, ND, ND, ND, NI, Z,Z,Z,Z,Z,Z, 1);
        tgemm<128,0,0,false><<<dim3(8, 32, 1), 256, S128>>>(ih, il, wrh, br + l*ND, 1.f,
            py, nullptr, nullptr, NI, NI, NI, ND, Z,Z,Z,Z,Z,Z, 1);
        add_ln_kernel<<<NBT, 256>>>(py, ln2g + l*ND, ln2b + l*ND);
    }

    tgemm<128,1,0,false><<<dim3(32, 7, NB), 256, S128>>>(xh + NM*ND, xl + NM*ND,
        wh + (ll)NL*WPL, bp, 1.f,
        out, nullptr, nullptr, ND, ND, ND, NOUT,
        (ll)NT*ND, Z, Z, Z, (ll)NS*NOUT, Z, 1);

    readout_kernel<<<(NB * NM * ND + 255) / 256, 256>>>(out);
}

// round 8
// speedup vs baseline: 6.8669x; 1.6633x over previous
#include <cuda_runtime.h>
#include <cuda_fp16.h>
#include <math.h>
#include <stdint.h>

#define NB   4
#define NS   896
#define ND   1024
#define NH   16
#define NDH  64
#define NI   4096
#define NOUT 4096
#define NL   2
#define NM   128
#define NT   1024
#define NBT  4096

typedef __half h16;
typedef long long ll;

__device__ float g_x[NBT * ND];
__device__ float g_y[NBT * ND];
__device__ h16  g_xh[NBT * ND];
__device__ h16  g_qh[NBT * ND];
__device__ h16  g_kh[NBT * ND];
__device__ h16  g_vth[NBT * ND];
__device__ h16  g_t0h[NBT * ND];
__device__ h16  g_ih[(size_t)NBT * NI];
#define WPL (4 * ND * ND + ND * NI + NI * ND)
#define WELEMS (NL * WPL + ND * NOUT)
__device__ h16  g_wh[WELEMS];

__device__ __forceinline__ uint32_t smem_u32(const void* p) {
    uint32_t a;
    asm("{ .reg .u64 t; cvta.to.shared.u64 t, %1; cvt.u32.u64 %0, t; }" : "=r"(a) : "l"(p));
    return a;
}
__device__ __forceinline__ float gelu_f(float x) {
    return 0.5f * x * (1.0f + erff(x * 0.7071067811865476f));
}
__device__ __forceinline__ void ldsm4(uint32_t& r0, uint32_t& r1, uint32_t& r2, uint32_t& r3, uint32_t a) {
    asm volatile("ldmatrix.sync.aligned.m8n8.x4.shared.b16 {%0,%1,%2,%3}, [%4];"
                 : "=r"(r0), "=r"(r1), "=r"(r2), "=r"(r3) : "r"(a));
}
__device__ __forceinline__ void mma16816(float* c, const uint32_t* a, const uint32_t* b) {
    asm volatile("mma.sync.aligned.m16n8k16.row.col.f32.f16.f16.f32 "
                 "{%0,%1,%2,%3},{%4,%5,%6,%7},{%8,%9},{%0,%1,%2,%3};"
                 : "+f"(c[0]), "+f"(c[1]), "+f"(c[2]), "+f"(c[3])
                 : "r"(a[0]), "r"(a[1]), "r"(a[2]), "r"(a[3]), "r"(b[0]), "r"(b[1]));
}
__device__ __forceinline__ void cpasync16(uint32_t dst, const void* src) {
    asm volatile("cp.async.cg.shared.global [%0], [%1], 16;" :: "r"(dst), "l"(src));
}
__device__ __forceinline__ void cpcommit() { asm volatile("cp.async.commit_group;" ::: "memory"); }
template<int N> __device__ __forceinline__ void cpwait() {
    asm volatile("cp.async.wait_group %0;" :: "n"(N) : "memory");
}
__device__ __forceinline__ uint32_t swoff(int r, int c16) {
    return (uint32_t)(r * 128 + ((c16 ^ (r & 7)) * 16));
}
__device__ __forceinline__ uint32_t packh(float a, float b) {
    __half2 p = __halves2half2(__float2half_rn(a), __float2half_rn(b));
    return *reinterpret_cast<uint32_t*>(&p);
}

// ---------------- fp16 warp-MMA GEMM (single term) ----------------
// D[128,BN] = act(alpha*(Ah[128,K] @ (Bh[BN,K])^T) + bias)
// OUTM: 0=fp32 C, 1=h16 C, 2=h16 transposed C (smem-staged)
template<int BN, int ACT, int OUTM>
__global__ void __launch_bounds__(256, 2) tgemm(
    const h16* __restrict__ Ah, const h16* __restrict__ Bh,
    const float* __restrict__ bias, float alpha,
    float* __restrict__ Cf, h16* __restrict__ Ch,
    int K, int lda, int ldb, int ldc,
    ll oA, ll iA, ll oB, ll iB, ll oC, ll iC, int h)
{
    constexpr int ABYTES = 128 * 128;
    constexpr int BBYTES = BN * 128;
    constexpr int STAGE  = ABYTES + BBYTES;
    constexpr int WN     = BN / 2;
    constexpr int NT8    = WN / 8;

    extern __shared__ __align__(128) char smem[];
    const uint32_t sb = smem_u32(smem);
    const int tid = threadIdx.x, lane = tid & 31, wid = tid >> 5;
    const int wm = wid >> 1, wn = wid & 1;

    const int z = blockIdx.z;
    const ll aoff = (ll)(z / h) * oA + (ll)(z % h) * iA;
    const ll boff = (ll)(z / h) * oB + (ll)(z % h) * iB;
    const ll coff = (ll)(z / h) * oC + (ll)(z % h) * iC;
    const int bm = blockIdx.y * 128;
    const int bn = blockIdx.x * BN;
    const h16* a0h = Ah + aoff + (ll)bm * lda;
    const h16* b0h = Bh + boff + (ll)bn * ldb;

    float acc[2][NT8][4];
#pragma unroll
    for (int i = 0; i < 2; i++)
#pragma unroll
        for (int j = 0; j < NT8; j++)
#pragma unroll
            for (int t = 0; t < 4; t++) acc[i][j][t] = 0.0f;

    const int nch = K >> 6;
    const int aRow = (lane & 7) | (((lane >> 3) & 1) << 3);
    const int aC   = lane >> 4;
    const int bRow = (lane & 7) | (((lane >> 4) & 1) << 3);
    const int bC   = (lane >> 3) & 1;

    auto issue = [&](int c, int s) {
        const int k0 = c * 64;
        const uint32_t base = sb + s * STAGE;
        constexpr int TOT = (128 + BN) * 8;
#pragma unroll 4
        for (int u = tid; u < TOT; u += 256) {
            const int chunk = u & 7, row = u >> 3;
            const h16* src; uint32_t dbase; int r, ld;
            if (row < 128) { src = a0h; r = row;       dbase = base;          ld = lda; }
            else           { src = b0h; r = row - 128; dbase = base + ABYTES; ld = ldb; }
            cpasync16(dbase + swoff(r, chunk), src + (ll)r * ld + k0 + chunk * 8);
        }
    };

    issue(0, 0);
    cpcommit();

    for (int c = 0; c < nch; c++) {
        if (c + 1 < nch) { issue(c + 1, (c + 1) & 1); cpcommit(); cpwait<1>(); }
        else             { cpwait<0>(); }
        __syncthreads();

        const uint32_t tAh = sb + (c & 1) * STAGE;
        const uint32_t tBh = tAh + ABYTES;

#pragma unroll
        for (int ks = 0; ks < 4; ks++) {
            uint32_t ah[2][4], bh[NT8][2];
#pragma unroll
            for (int mt = 0; mt < 2; mt++) {
                const int r = wm * 32 + mt * 16 + aRow;
                const int c16 = ks * 2 + aC;
                ldsm4(ah[mt][0], ah[mt][1], ah[mt][2], ah[mt][3], tAh + swoff(r, c16));
            }
#pragma unroll
            for (int nt2 = 0; nt2 < NT8 / 2; nt2++) {
                const int r = wn * WN + nt2 * 16 + bRow;
                const int c16 = ks * 2 + bC;
                ldsm4(bh[2*nt2][0], bh[2*nt2][1], bh[2*nt2+1][0], bh[2*nt2+1][1], tBh + swoff(r, c16));
            }
#pragma unroll
            for (int mt = 0; mt < 2; mt++)
#pragma unroll
                for (int nt = 0; nt < NT8; nt++)
                    mma16816(acc[mt][nt], ah[mt], bh[nt]);
        }
        __syncthreads();
    }

    const int gid = lane >> 2, tig2 = (lane & 3) * 2;

    if (OUTM == 2) {
        constexpr int TSTRIDE = 272;
#pragma unroll
        for (int mt = 0; mt < 2; mt++)
#pragma unroll
            for (int nt = 0; nt < NT8; nt++) {
                const int nl = wn * WN + nt * 8 + tig2;
#pragma unroll
                for (int hf = 0; hf < 2; hf++) {
                    const int ml = wm * 32 + mt * 16 + gid + hf * 8;
                    *reinterpret_cast<h16*>(smem + nl * TSTRIDE + ml * 2) =
                        __float2half_rn(acc[mt][nt][hf * 2] * alpha);
                    *reinterpret_cast<h16*>(smem + (nl + 1) * TSTRIDE + ml * 2) =
                        __float2half_rn(acc[mt][nt][hf * 2 + 1] * alpha);
                }
            }
        __syncthreads();
        for (int u = tid; u < BN * 16; u += 256) {
            const int nl = u >> 4, c16 = (u & 15) * 8;
            uint4 v = *reinterpret_cast<const uint4*>(smem + nl * TSTRIDE + c16 * 2);
            if (bias) {
                h16* hv = reinterpret_cast<h16*>(&v);
                const float bb = bias[bn + nl];
#pragma unroll
                for (int t = 0; t < 8; t++) hv[t] = __float2half_rn(__half2float(hv[t]) + bb);
            }
            *reinterpret_cast<uint4*>(Ch + coff + (ll)(bn + nl) * ldc + bm + c16) = v;
        }
        return;
    }

#pragma unroll
    for (int mt = 0; mt < 2; mt++) {
#pragma unroll
        for (int nt = 0; nt < NT8; nt++) {
            const int n = bn + wn * WN + nt * 8 + tig2;
            float bv0 = 0.f, bv1 = 0.f;
            if (bias) { bv0 = bias[n]; bv1 = bias[n + 1]; }
#pragma unroll
            for (int hf = 0; hf < 2; hf++) {
                const int m = bm + wm * 32 + mt * 16 + gid + hf * 8;
                float v0 = acc[mt][nt][hf * 2]     * alpha + bv0;
                float v1 = acc[mt][nt][hf * 2 + 1] * alpha + bv1;
                if (ACT) { v0 = gelu_f(v0); v1 = gelu_f(v1); }
                if (OUTM == 0) {
                    *reinterpret_cast<float2*>(Cf + coff + (ll)m * ldc + n) = make_float2(v0, v1);
                } else {
                    __half2 H = __halves2half2(__float2half_rn(v0), __float2half_rn(v1));
                    *reinterpret_cast<__half2*>(Ch + coff + (ll)m * ldc + n) = H;
                }
            }
        }
    }
}

// ---------------- fused flash attention (single-term fp16, log2-domain softmax) ----------------
// grid (8, 64): x = q block, y = b*NH+h. 8 warps: wm 0..3 (32 rows), wn 0..1 (64 S cols).
#define FSMEM 84480
__global__ void __launch_bounds__(256, 1) flash_kernel(
    const h16* __restrict__ Qh, const h16* __restrict__ Kh,
    const h16* __restrict__ Vt, h16* __restrict__ Oh)
{
    extern __shared__ __align__(128) char smem[];
    const uint32_t sb = smem_u32(smem);
    const int tid = threadIdx.x, lane = tid & 31, wid = tid >> 5;
    const int wm = wid >> 1, wn = wid & 1;
    const int qb = blockIdx.x;
    const int z = blockIdx.y, b = z >> 4, hh = z & 15;

    const h16* q0 = Qh + (ll)(b * NT + qb * 128) * ND + hh * 64;
    const h16* k0 = Kh + (ll)(b * NT) * ND + hh * 64;
    const h16* v0 = Vt + (ll)(hh * 64) * NBT + b * NT;

    for (int u = tid; u < 1024; u += 256) {
        int r = u >> 3, c = u & 7;
        cpasync16(sb + swoff(r, c), q0 + (ll)r * ND + c * 8);
    }
    auto issueKV = [&](int t) {
        const int s = t & 1;
        const uint32_t kb = sb + 16384 + s * 16384;
        const uint32_t vb = sb + 49152 + s * 16384;
        for (int u = tid; u < 1024; u += 256) {
            int r = u >> 3, c = u & 7;
            cpasync16(kb + swoff(r, c), k0 + (ll)(t * 128 + r) * ND + c * 8);
        }
        for (int u = tid; u < 1024; u += 256) {
            int half = u >> 9, r = (u >> 3) & 63, c = u & 7;
            cpasync16(vb + half * 8192 + swoff(r, c),
                      v0 + (ll)r * NBT + t * 128 + half * 64 + c * 8);
        }
    };
    issueKV(0); cpcommit();

    const int aRow = (lane & 7) | (((lane >> 3) & 1) << 3);
    const int aC   = lane >> 4;
    const int bRow = (lane & 7) | (((lane >> 4) & 1) << 3);
    const int bC   = (lane >> 3) & 1;
    const int gid  = lane >> 2, tig2 = (lane & 3) * 2;

    const float SCL = 0.125f * 1.4426950408889634f;   // /sqrt(64) * log2(e)

    float oacc[2][8][4];
#pragma unroll
    for (int i = 0; i < 2; i++)
#pragma unroll
        for (int j = 0; j < 8; j++)
#pragma unroll
            for (int t = 0; t < 4; t++) oacc[i][j][t] = 0.0f;
    float mrow[2][2] = {{-1e30f, -1e30f}, {-1e30f, -1e30f}};
    float lsum[2][2] = {{0.f, 0.f}, {0.f, 0.f}};

    float* redmax = (float*)(smem + 81920);
    float* redsum = (float*)(smem + 82944);

    for (int t = 0; t < 8; t++) {
        if (t < 7) { issueKV(t + 1); cpcommit(); cpwait<1>(); }
        else       { cpwait<0>(); }
        __syncthreads();
        const uint32_t kb = sb + 16384 + (t & 1) * 16384;
        const uint32_t vb = sb + 49152 + (t & 1) * 16384 + wn * 8192;

        float sacc[2][8][4];
#pragma unroll
        for (int i = 0; i < 2; i++)
#pragma unroll
            for (int j = 0; j < 8; j++)
#pragma unroll
                for (int u = 0; u < 4; u++) sacc[i][j][u] = 0.0f;

#pragma unroll
        for (int kc = 0; kc < 4; kc++) {
            uint32_t ah[2][4], bh[8][2];
#pragma unroll
            for (int mt = 0; mt < 2; mt++) {
                const int r = wm * 32 + mt * 16 + aRow;
                const int c16 = kc * 2 + aC;
                ldsm4(ah[mt][0], ah[mt][1], ah[mt][2], ah[mt][3], sb + swoff(r, c16));
            }
#pragma unroll
            for (int nt2 = 0; nt2 < 4; nt2++) {
                const int r = wn * 64 + nt2 * 16 + bRow;
                const int c16 = kc * 2 + bC;
                ldsm4(bh[2*nt2][0], bh[2*nt2][1], bh[2*nt2+1][0], bh[2*nt2+1][1], kb + swoff(r, c16));
            }
#pragma unroll
            for (int mt = 0; mt < 2; mt++)
#pragma unroll
                for (int nt = 0; nt < 8; nt++)
                    mma16816(sacc[mt][nt], ah[mt], bh[nt]);
        }
#pragma unroll
        for (int i = 0; i < 2; i++)
#pragma unroll
            for (int j = 0; j < 8; j++)
#pragma unroll
                for (int u = 0; u < 4; u++) sacc[i][j][u] *= SCL;

        float pmax[2][2];
#pragma unroll
        for (int mt = 0; mt < 2; mt++)
#pragma unroll
            for (int hf = 0; hf < 2; hf++) {
                float v = -1e30f;
#pragma unroll
                for (int nt = 0; nt < 8; nt++)
                    v = fmaxf(v, fmaxf(sacc[mt][nt][hf*2], sacc[mt][nt][hf*2+1]));
                v = fmaxf(v, __shfl_xor_sync(0xffffffffu, v, 1));
                v = fmaxf(v, __shfl_xor_sync(0xffffffffu, v, 2));
                pmax[mt][hf] = v;
            }
        if ((lane & 3) == 0) {
#pragma unroll
            for (int mt = 0; mt < 2; mt++)
#pragma unroll
                for (int hf = 0; hf < 2; hf++)
                    redmax[wn * 128 + wm*32 + mt*16 + hf*8 + gid] = pmax[mt][hf];
        }
        __syncthreads();
        float scl[2][2];
#pragma unroll
        for (int mt = 0; mt < 2; mt++)
#pragma unroll
            for (int hf = 0; hf < 2; hf++) {
                const int r = wm*32 + mt*16 + hf*8 + gid;
                float tm = fmaxf(pmax[mt][hf], redmax[(wn^1) * 128 + r]);
                float mi = fmaxf(mrow[mt][hf], tm);
                scl[mt][hf] = exp2f(mrow[mt][hf] - mi);
                mrow[mt][hf] = mi;
            }
        float psum[2][2] = {{0.f,0.f},{0.f,0.f}};
#pragma unroll
        for (int mt = 0; mt < 2; mt++)
#pragma unroll
            for (int nt = 0; nt < 8; nt++)
#pragma unroll
                for (int j = 0; j < 4; j++) {
                    const int hf = j >> 1;
                    float p = exp2f(sacc[mt][nt][j] - mrow[mt][hf]);
                    sacc[mt][nt][j] = p;
                    psum[mt][hf] += p;
                }
#pragma unroll
        for (int mt = 0; mt < 2; mt++)
#pragma unroll
            for (int hf = 0; hf < 2; hf++) {
                psum[mt][hf] += __shfl_xor_sync(0xffffffffu, psum[mt][hf], 1);
                psum[mt][hf] += __shfl_xor_sync(0xffffffffu, psum[mt][hf], 2);
            }
        __syncthreads();
        if ((lane & 3) == 0) {
#pragma unroll
            for (int mt = 0; mt < 2; mt++)
#pragma unroll
                for (int hf = 0; hf < 2; hf++)
                    redsum[wn * 128 + wm*32 + mt*16 + hf*8 + gid] = psum[mt][hf];
        }
        __syncthreads();
#pragma unroll
        for (int mt = 0; mt < 2; mt++)
#pragma unroll
            for (int hf = 0; hf < 2; hf++) {
                const int r = wm*32 + mt*16 + hf*8 + gid;
                float tot = psum[mt][hf] + redsum[(wn^1) * 128 + r];
                lsum[mt][hf] = lsum[mt][hf] * scl[mt][hf] + tot;
            }
#pragma unroll
        for (int mt = 0; mt < 2; mt++)
#pragma unroll
            for (int dt = 0; dt < 8; dt++)
#pragma unroll
                for (int j = 0; j < 4; j++) oacc[mt][dt][j] *= scl[mt][j >> 1];

#pragma unroll
        for (int kk = 0; kk < 4; kk++) {
            uint32_t bfr[8][2];
#pragma unroll
            for (int dt2 = 0; dt2 < 4; dt2++) {
                const int r = dt2 * 16 + bRow;
                const int c16 = kk * 2 + bC;
                ldsm4(bfr[2*dt2][0], bfr[2*dt2][1], bfr[2*dt2+1][0], bfr[2*dt2+1][1], vb + swoff(r, c16));
            }
            uint32_t aH[2][4];
#pragma unroll
            for (int mt = 0; mt < 2; mt++)
#pragma unroll
                for (int q = 0; q < 4; q++) {
                    const int nt = 2 * kk + (q >> 1);
                    const int j0 = (q & 1) * 2;
                    aH[mt][q] = packh(sacc[mt][nt][j0], sacc[mt][nt][j0 + 1]);
                }
#pragma unroll
            for (int mt = 0; mt < 2; mt++)
#pragma unroll
                for (int dt = 0; dt < 8; dt++)
                    mma16816(oacc[mt][dt], aH[mt], bfr[dt]);
        }
        __syncthreads();
    }

    float* lb = (float*)(smem + 83968);
    if (wn == 0 && (lane & 3) == 0) {
#pragma unroll
        for (int mt = 0; mt < 2; mt++)
#pragma unroll
            for (int hf = 0; hf < 2; hf++)
                lb[wm*32 + mt*16 + hf*8 + gid] = lsum[mt][hf];
    }
    float* obuf = (float*)smem;
    const int OST = 68;
    if (wn == 0) {
#pragma unroll
        for (int mt = 0; mt < 2; mt++)
#pragma unroll
            for (int dt = 0; dt < 8; dt++)
#pragma unroll
                for (int j = 0; j < 4; j++)
                    obuf[(wm*32 + mt*16 + (j>>1)*8 + gid) * OST + dt*8 + tig2 + (j&1)] = oacc[mt][dt][j];
    }
    __syncthreads();
    if (wn == 1) {
#pragma unroll
        for (int mt = 0; mt < 2; mt++)
#pragma unroll
            for (int dt = 0; dt < 8; dt++)
#pragma unroll
                for (int j = 0; j < 4; j++)
                    obuf[(wm*32 + mt*16 + (j>>1)*8 + gid) * OST + dt*8 + tig2 + (j&1)] += oacc[mt][dt][j];
    }
    __syncthreads();
    h16* oh = Oh + (ll)(b * NT + qb * 128) * ND + hh * 64;
    for (int u = tid; u < 8192; u += 256) {
        const int r = u >> 6, d = u & 63;
        oh[(ll)r * ND + d] = __float2half_rn(obuf[r * OST + d] / lb[r]);
    }
}

// W[K,N] -> Th[N,K]
__global__ void __launch_bounds__(256) wsplit_kernel(const float* __restrict__ W,
                                                     h16* __restrict__ Th, int K, int N) {
    __shared__ float t[32][33];
    const int n0 = blockIdx.x * 32, k0 = blockIdx.y * 32;
    const int tx = threadIdx.x, ty = threadIdx.y;
#pragma unroll
    for (int i = 0; i < 4; i++)
        t[ty + i * 8][tx] = W[(ll)(k0 + ty + i * 8) * N + n0 + tx];
    __syncthreads();
#pragma unroll
    for (int i = 0; i < 4; i++) {
        int n = ty + i * 8;
        Th[(ll)(n0 + n) * K + k0 + tx] = __float2half_rn(t[tx][n]);
    }
}

__global__ void concat_kernel(const float* __restrict__ hs, const float* __restrict__ mem) {
    int i4 = blockIdx.x * blockDim.x + threadIdx.x;
    if (i4 >= NBT * ND / 4) return;
    int idx = i4 * 4;
    int d = idx % ND;
    int t = (idx / ND) % NT;
    int b = idx / (ND * NT);
    float4 v = (t < NM) ? *reinterpret_cast<const float4*>(mem + t * ND + d)
                        : *reinterpret_cast<const float4*>(hs + ((size_t)(b * NS + t - NM)) * ND + d);
    *reinterpret_cast<float4*>(g_x + idx) = v;
    *reinterpret_cast<__half2*>(g_xh + idx)     = __halves2half2(__float2half_rn(v.x), __float2half_rn(v.y));
    *reinterpret_cast<__half2*>(g_xh + idx + 2) = __halves2half2(__float2half_rn(v.z), __float2half_rn(v.w));
}

__global__ void __launch_bounds__(256) add_ln_kernel(const float* __restrict__ y,
                                                     const float* __restrict__ gam,
                                                     const float* __restrict__ bet) {
    __shared__ float red[8];
    __shared__ float s0, s1;
    const int tid = threadIdx.x;
    const size_t base = (size_t)blockIdx.x * ND;
    const int c = tid * 4;
    float4 a = *reinterpret_cast<const float4*>(y + base + c);
    float4 xo = *reinterpret_cast<const float4*>(g_x + base + c);
    float v0 = a.x + xo.x, v1 = a.y + xo.y, v2 = a.z + xo.z, v3 = a.w + xo.w;
    float s = v0 + v1 + v2 + v3;
    for (int o = 16; o > 0; o >>= 1) s += __shfl_xor_sync(0xffffffffu, s, o);
    if ((tid & 31) == 0) red[tid >> 5] = s;
    __syncthreads();
    if (tid == 0) { float t = 0; for (int i = 0; i < 8; i++) t += red[i]; s0 = t * (1.0f / ND); }
    __syncthreads();
    const float mean = s0;
    float d0 = v0 - mean, d1 = v1 - mean, d2 = v2 - mean, d3 = v3 - mean;
    float vs = d0*d0 + d1*d1 + d2*d2 + d3*d3;
    for (int o = 16; o > 0; o >>= 1) vs += __shfl_xor_sync(0xffffffffu, vs, o);
    if ((tid & 31) == 0) red[tid >> 5] = vs;
    __syncthreads();
    if (tid == 0) { float t = 0; for (int i = 0; i < 8; i++) t += red[i]; s1 = rsqrtf(t * (1.0f / ND) + 1e-12f); }
    __syncthreads();
    const float inv = s1;
    float4 gv = *reinterpret_cast<const float4*>(gam + c);
    float4 bv = *reinterpret_cast<const float4*>(bet + c);
    float r0 = d0*inv*gv.x + bv.x, r1 = d1*inv*gv.y + bv.y;
    float r2 = d2*inv*gv.z + bv.z, r3 = d3*inv*gv.w + bv.w;
    *reinterpret_cast<float4*>(g_x + base + c) = make_float4(r0, r1, r2, r3);
    *reinterpret_cast<__half2*>(g_xh + base + c)     = __halves2half2(__float2half_rn(r0), __float2half_rn(r1));
    *reinterpret_cast<__half2*>(g_xh + base + c + 2) = __halves2half2(__float2half_rn(r2), __float2half_rn(r3));
}

__global__ void readout_kernel(float* __restrict__ out) {
    int idx = blockIdx.x * blockDim.x + threadIdx.x;
    if (idx >= NB * NM * ND) return;
    int d = idx % ND;
    int t = (idx / ND) % NM;
    int b = idx / (ND * NM);
    out[(size_t)NB * NS * NOUT + idx] = g_x[((size_t)b * NT + t) * ND + d];
}

#define S128 (2 * (128 * 128 + 128 * 128))   // 65536

extern "C" void kernel_launch(void* const* d_in, const int* in_sizes, int n_in,
                              void* d_out, int out_size) {
    const float* hs   = (const float*)d_in[0];
    const float* mem  = (const float*)d_in[1];
    const float* Wq   = (const float*)d_in[2];
    const float* bq   = (const float*)d_in[3];
    const float* Wk   = (const float*)d_in[4];
    const float* bk   = (const float*)d_in[5];
    const float* Wv   = (const float*)d_in[6];
    const float* bv   = (const float*)d_in[7];
    const float* Wo   = (const float*)d_in[8];
    const float* bo   = (const float*)d_in[9];
    const float* ln1g = (const float*)d_in[10];
    const float* ln1b = (const float*)d_in[11];
    const float* Wm   = (const float*)d_in[12];
    const float* bmv  = (const float*)d_in[13];
    const float* Wr   = (const float*)d_in[14];
    const float* br   = (const float*)d_in[15];
    const float* ln2g = (const float*)d_in[16];
    const float* ln2b = (const float*)d_in[17];
    const float* Wp   = (const float*)d_in[18];
    const float* bp   = (const float*)d_in[19];
    float* out = (float*)d_out;

    static h16 *wh = nullptr, *xh, *qh, *kh, *vth, *t0h, *ih;
    static float *px, *py;
    if (!wh) {
        cudaGetSymbolAddress((void**)&wh, g_wh);
        cudaGetSymbolAddress((void**)&xh, g_xh);
        cudaGetSymbolAddress((void**)&qh, g_qh);
        cudaGetSymbolAddress((void**)&kh, g_kh);
        cudaGetSymbolAddress((void**)&vth, g_vth);
        cudaGetSymbolAddress((void**)&t0h, g_t0h);
        cudaGetSymbolAddress((void**)&ih, g_ih);
        cudaGetSymbolAddress((void**)&px, g_x);
        cudaGetSymbolAddress((void**)&py, g_y);
        cudaFuncSetAttribute((const void*)tgemm<128,0,0>, cudaFuncAttributeMaxDynamicSharedMemorySize, S128);
        cudaFuncSetAttribute((const void*)tgemm<128,0,1>, cudaFuncAttributeMaxDynamicSharedMemorySize, S128);
        cudaFuncSetAttribute((const void*)tgemm<128,0,2>, cudaFuncAttributeMaxDynamicSharedMemorySize, S128);
        cudaFuncSetAttribute((const void*)tgemm<128,1,1>, cudaFuncAttributeMaxDynamicSharedMemorySize, S128);
        cudaFuncSetAttribute((const void*)tgemm<128,1,0>, cudaFuncAttributeMaxDynamicSharedMemorySize, S128);
        cudaFuncSetAttribute((const void*)flash_kernel, cudaFuncAttributeMaxDynamicSharedMemorySize, FSMEM);
    }

    const ll Z = 0;
    const ll DD = (ll)ND * ND;
    dim3 t32(32, 8);

    for (int l = 0; l < NL; l++) {
        ll o = (ll)l * WPL;
        wsplit_kernel<<<dim3(ND/32, ND/32), t32>>>(Wq + l*DD, wh + o,        ND, ND);
        wsplit_kernel<<<dim3(ND/32, ND/32), t32>>>(Wk + l*DD, wh + o + DD,   ND, ND);
        wsplit_kernel<<<dim3(ND/32, ND/32), t32>>>(Wv + l*DD, wh + o + 2*DD, ND, ND);
        wsplit_kernel<<<dim3(ND/32, ND/32), t32>>>(Wo + l*DD, wh + o + 3*DD, ND, ND);
        wsplit_kernel<<<dim3(NI/32, ND/32), t32>>>(Wm + (ll)l*ND*NI, wh + o + 4*DD, ND, NI);
        wsplit_kernel<<<dim3(ND/32, NI/32), t32>>>(Wr + (ll)l*NI*ND, wh + o + 4*DD + (ll)ND*NI, NI, ND);
    }
    wsplit_kernel<<<dim3(NOUT/32, ND/32), t32>>>(Wp, wh + (ll)NL*WPL, ND, NOUT);

    concat_kernel<<<(NBT * ND / 4 + 255) / 256, 256>>>(hs, mem);

    for (int l = 0; l < NL; l++) {
        ll o = (ll)l * WPL;
        const h16 *wqh = wh + o;
        const h16 *wkh = wh + o + DD;
        const h16 *wvh = wh + o + 2*DD;
        const h16 *woh = wh + o + 3*DD;
        const h16 *wmh = wh + o + 4*DD;
        const h16 *wrh = wh + o + 4*DD + (ll)ND*NI;

        tgemm<128,0,1><<<dim3(8, 32, 1), 256, S128>>>(xh, wqh, bq + l*ND, 1.f,
            nullptr, qh, ND, ND, ND, ND, Z,Z,Z,Z,Z,Z, 1);
        tgemm<128,0,1><<<dim3(8, 32, 1), 256, S128>>>(xh, wkh, bk + l*ND, 1.f,
            nullptr, kh, ND, ND, ND, ND, Z,Z,Z,Z,Z,Z, 1);
        tgemm<128,0,2><<<dim3(8, 32, 1), 256, S128>>>(xh, wvh, bv + l*ND, 1.f,
            nullptr, vth, ND, ND, ND, NBT, Z,Z,Z,Z,Z,Z, 1);

        flash_kernel<<<dim3(8, 64), 256, FSMEM>>>(qh, kh, vth, t0h);

        tgemm<128,0,0><<<dim3(8, 32, 1), 256, S128>>>(t0h, woh, bo + l*ND, 1.f,
            py, nullptr, ND, ND, ND, ND, Z,Z,Z,Z,Z,Z, 1);
        add_ln_kernel<<<NBT, 256>>>(py, ln1g + l*ND, ln1b + l*ND);

        tgemm<128,1,1><<<dim3(32, 32, 1), 256, S128>>>(xh, wmh, bmv + l*NI, 1.f,
            nullptr, ih, ND, ND, ND, NI, Z,Z,Z,Z,Z,Z, 1);
        tgemm<128,0,0><<<dim3(8, 32, 1), 256, S128>>>(ih, wrh, br + l*ND, 1.f,
            py, nullptr, NI, NI, NI, ND, Z,Z,Z,Z,Z,Z, 1);
        add_ln_kernel<<<NBT, 256>>>(py, ln2g + l*ND, ln2b + l*ND);
    }

    tgemm<128,1,0><<<dim3(32, 7, NB), 256, S128>>>(xh + NM*ND,
        wh + (ll)NL*WPL, bp, 1.f,
        out, nullptr, ND, ND, ND, NOUT,
        (ll)NT*ND, Z, Z, Z, (ll)NS*NOUT, Z, 1);

    readout_kernel<<<(NB * NM * ND + 255) / 256, 256>>>(out);
}